// round 13
// baseline (speedup 1.0000x reference)
#include <cuda_runtime.h>
#include <cuda_fp16.h>
#include <cstdint>
#include <math.h>

#define EPSBN 1e-3f

// ---------------- device scratch (no allocation allowed) ----------------
__device__ __align__(16) float  g_Pi_a[2048 * 256];
__device__ __align__(16) float  g_Pj_a[2048 * 256];
__device__ __align__(16) float  g_Pi_m[2048 * 256];
__device__ __align__(16) float  g_Pj_m[2048 * 256];
__device__ __align__(16) float  g_Pu [2048 * 256];
__device__ __align__(16) float  g_aggA[2048 * 128];   // partial agg, rows 0-63
__device__ __align__(16) float  g_aggB[2048 * 128];   // partial agg, rows 64-127
// slabs: g0/g1/g3/g4: [n=128][k=128]; g2/g5: [n=128][k=256]  (B[n][k]=W[k][n])
__device__ __align__(16) __half g_WT[131072];
__constant__ int c_OW[6] = {0, 16384, 32768, 65536, 81920, 98304};  // half offsets

// ---------------- PTX helpers (baseline sm_80+, safe for sm_103) --------
__device__ __forceinline__ uint32_t smem_u32(const void* p) {
    uint32_t a;
    asm("{ .reg .u64 t; cvta.to.shared.u64 t, %1; cvt.u32.u64 %0, t; }" : "=r"(a) : "l"(p));
    return a;
}
__device__ __forceinline__ void cp16(uint32_t s, const void* g) {
    asm volatile("cp.async.cg.shared.global [%0], [%1], 16;" :: "r"(s), "l"(g));
}
#define CP_COMMIT() asm volatile("cp.async.commit_group;" ::: "memory")
#define CP_WAIT0()  asm volatile("cp.async.wait_group 0;" ::: "memory")

__device__ __forceinline__ void ldsm4(uint32_t& r0, uint32_t& r1, uint32_t& r2, uint32_t& r3,
                                      uint32_t addr) {
    asm volatile("ldmatrix.sync.aligned.m8n8.x4.shared.b16 {%0,%1,%2,%3}, [%4];"
                 : "=r"(r0), "=r"(r1), "=r"(r2), "=r"(r3) : "r"(addr));
}
__device__ __forceinline__ void mma16816(float* c, const uint32_t* a, uint32_t b0, uint32_t b1) {
    asm volatile("mma.sync.aligned.m16n8k16.row.col.f32.f16.f16.f32 "
                 "{%0,%1,%2,%3},{%4,%5,%6,%7},{%8,%9},{%0,%1,%2,%3};"
                 : "+f"(c[0]), "+f"(c[1]), "+f"(c[2]), "+f"(c[3])
                 : "r"(a[0]), "r"(a[1]), "r"(a[2]), "r"(a[3]), "r"(b0), "r"(b1));
}

// ---------------- SMEM layout (bytes) ----------------
// sA: 64 x (128+8) f16 ; sH: 64 x (256+8) f16 ; sB: 128 n x (128+8) k f16
#define LDAE 136
#define LDH  264
#define OFF_A    0u         // 17408
#define OFF_H    17408u     // 33792
#define OFF_B    51200u     // 34816
#define OFF_BIAS 86016u     // 128 f32
#define OFF_MASK 86528u     // 64 f32
#define OFF_SCL  86784u     // 128 f32
#define OFF_SHF  87296u     // 128 f32
#define OFF_RED  87808u     // 2 x 128 f32
#define SMEM_EDGE_BYTES 88832u

#define THREADS_EDGE 128

// ---------------------------------------------------------------------------
// prep: blocks 0..639 -> Pi_a/Pj_a/Pi_m/Pj_m/Pu ; blocks 640..647 -> g_WT
// ---------------------------------------------------------------------------
__global__ __launch_bounds__(256) void prep_kernel(
    const float* __restrict__ nodes,
    const float* __restrict__ W1a, const float* __restrict__ W2a,
    const float* __restrict__ W1m, const float* __restrict__ W2m,
    const float* __restrict__ W1u)
{
    int blk = blockIdx.x, tid = threadIdx.x;
    if (blk < 640) {
        __shared__ float sX[2048];
        int m = blk >> 7, row0 = (blk & 127) * 16;
        for (int i = tid; i < 2048; i += 256) sX[i] = nodes[(size_t)row0 * 128 + i];
        __syncthreads();
        const float* W;
        float* O;
        switch (m) {
            case 0: W = W1a;             O = g_Pi_a; break;
            case 1: W = W1a + 128 * 256; O = g_Pj_a; break;
            case 2: W = W1m;             O = g_Pi_m; break;
            case 3: W = W1m + 128 * 256; O = g_Pj_m; break;
            default: W = W1u;            O = g_Pu;   break;
        }
        W += tid;
        O += (size_t)row0 * 256 + tid;
        float a[16];
        #pragma unroll
        for (int r = 0; r < 16; r++) a[r] = 0.f;
        #pragma unroll 2
        for (int kb = 0; kb < 128; kb += 4) {
            float w0 = W[(size_t)(kb + 0) * 256];
            float w1 = W[(size_t)(kb + 1) * 256];
            float w2 = W[(size_t)(kb + 2) * 256];
            float w3 = W[(size_t)(kb + 3) * 256];
            #pragma unroll
            for (int r = 0; r < 16; r++) {
                float4 xv = *(const float4*)(sX + r * 128 + kb);
                a[r] += xv.x * w0 + xv.y * w1 + xv.z * w2 + xv.w * w3;
            }
        }
        #pragma unroll
        for (int r = 0; r < 16; r++) O[(size_t)r * 256] = a[r];
        return;
    }
    int c = blk - 640;  // 0..7
    int slab, nbase;
    if      (c == 0) { slab = 0; nbase = 0; }
    else if (c == 1) { slab = 1; nbase = 0; }
    else if (c <= 3) { slab = 2; nbase = (c - 2) * 64; }
    else if (c == 4) { slab = 3; nbase = 0; }
    else if (c == 5) { slab = 4; nbase = 0; }
    else             { slab = 5; nbase = (c - 6) * 64; }
    int K = (slab == 2 || slab == 5) ? 256 : 128;
    int nrows = (slab == 2 || slab == 5) ? 64 : 128;
    __half* dst = g_WT + c_OW[slab] + (size_t)nbase * K;
    for (int e = tid; e < nrows * K; e += 256) {
        int n = nbase + e / K;
        int k = e % K;
        float v;
        if      (slab == 0) v = W1a[(size_t)(256 + k) * 256 + n];
        else if (slab == 1) v = W1a[(size_t)(256 + k) * 256 + 128 + n];
        else if (slab == 2) v = W2a[(size_t)k * 128 + n];
        else if (slab == 3) v = W1m[(size_t)(256 + k) * 256 + n];
        else if (slab == 4) v = W1m[(size_t)(256 + k) * 256 + 128 + n];
        else                v = W2m[(size_t)k * 128 + n];
        dst[e] = __float2half_rn(v);
    }
}

// ---------------------------------------------------------------------------
// edge kernel: M=64 tile, 4 warps of 32x64, 8 K=128 chunk phases, 2 CTAs/SM
// chunk -> (slab, khalf): 0:(0,0) 1:(1,0) 2:(2,0) 3:(2,1) 4:(3,0) 5:(4,0) 6:(5,0) 7:(5,1)
// ---------------------------------------------------------------------------
__device__ __forceinline__ void cp_chunk(uint32_t sbase, int i, int tid) {
    static const int chS[8] = {0, 1, 2, 2, 3, 4, 5, 5};
    static const int chH[8] = {0, 0, 0, 1, 0, 0, 0, 1};
    int s = chS[i], h = chH[i];
    int K = (s == 2 || s == 5) ? 256 : 128;
    const __half* src = g_WT + c_OW[s] + h * 128;
    #pragma unroll
    for (int j = 0; j < 16; j++) {
        int f = tid + j * THREADS_EDGE;
        int n = f >> 4, sub = f & 15;
        cp16(sbase + OFF_B + (uint32_t)(n * (LDAE * 2) + sub * 16),
             src + (size_t)n * K + sub * 8);
    }
    CP_COMMIT();
}

// 32x64 warp tile, K=128 chunk
template <int LDA_>
__device__ __forceinline__ void kloop(uint32_t aBase, uint32_t bBase,
                                      int m0, int n0, int aRow, int aK, int bRow, int bK,
                                      float (&acc)[2][8][4])
{
    #pragma unroll 4
    for (int kt = 0; kt < 8; kt++) {
        int kg = kt * 16;
        uint32_t a0[4], a1[4], bf[16];
        ldsm4(a0[0], a0[1], a0[2], a0[3],
              aBase + (uint32_t)(((m0 + aRow) * LDA_ + kg + aK) << 1));
        ldsm4(a1[0], a1[1], a1[2], a1[3],
              aBase + (uint32_t)(((m0 + 16 + aRow) * LDA_ + kg + aK) << 1));
        #pragma unroll
        for (int pp = 0; pp < 4; pp++)
            ldsm4(bf[pp * 4], bf[pp * 4 + 1], bf[pp * 4 + 2], bf[pp * 4 + 3],
                  bBase + (uint32_t)(((n0 + pp * 16 + bRow) * LDAE + kg + bK) << 1));
        #pragma unroll
        for (int nt = 0; nt < 8; nt++) {
            uint32_t bb0 = bf[(nt >> 1) * 4 + (nt & 1) * 2];
            uint32_t bb1 = bf[(nt >> 1) * 4 + (nt & 1) * 2 + 1];
            mma16816(acc[0][nt], a0, bb0, bb1);
            mma16816(acc[1][nt], a1, bb0, bb1);
        }
    }
}

__global__ __launch_bounds__(THREADS_EDGE, 2) void edge_kernel(
    const float* __restrict__ edges, const float* __restrict__ mask,
    const float* __restrict__ b1a, const float* __restrict__ b2a,
    const float* __restrict__ b1m, const float* __restrict__ b2m,
    const float* __restrict__ gamma_e, const float* __restrict__ beta_e,
    const float* __restrict__ mean_e,  const float* __restrict__ var_e,
    float* __restrict__ edges_out)
{
    extern __shared__ char smc[];
    uint32_t sbase = smem_u32(smc);
    int p = blockIdx.x >> 1, half = blockIdx.x & 1, bb = blockIdx.y;
    int tid = threadIdx.x, lane = tid & 31, w = tid >> 5;
    int wm = w >> 1, wn = w & 1;          // 2 x 2 warp grid, 32x64 tiles
    int m0 = wm * 32, n0 = wn * 64;

    float* sBias = (float*)(smc + OFF_BIAS);
    float* sMask = (float*)(smc + OFF_MASK);
    float* sScl  = (float*)(smc + OFF_SCL);
    float* sShf  = (float*)(smc + OFF_SHF);
    float* sRed  = (float*)(smc + OFF_RED);

    int aRow = lane & 15;
    int aK   = (lane & 16) ? 8 : 0;
    int bRow = (lane & 7) + ((lane & 16) ? 8 : 0);
    int bK   = (lane & 8) ? 8 : 0;
    int tq = lane >> 2;
    int tc = (lane & 3) * 2;

    cp_chunk(sbase, 0, tid);   // prefetch chunk 0 (overlaps E-tile load)

    const size_t tb   = (size_t)(bb * 128 + p) * 256;
    const size_t pib  = (size_t)bb * 128 * 256;
    const int    row0 = half * 64;                 // global row base of this CTA

    // ---- load E tile (64 rows, fp16) + consts
    {
        const float4* Eg = (const float4*)(edges +
            (size_t)(bb * 16384 + p * 128 + row0) * 128);
        #pragma unroll 4
        for (int i = tid; i < 2048; i += THREADS_EDGE) {
            int qq = i >> 5, k4 = (i & 31) << 2;
            float4 e = __ldg(Eg + i);
            __half2 e0 = __floats2half2_rn(e.x, e.y), e1 = __floats2half2_rn(e.z, e.w);
            *(uint2*)(smc + OFF_A + (size_t)((qq * LDAE + k4) << 1)) =
                make_uint2(*(uint32_t*)&e0, *(uint32_t*)&e1);
        }
        if (tid < 64)
            sMask[tid] = __ldg(mask + (size_t)bb * 16384 + p * 128 + row0 + tid);
        {
            int c = tid;
            float s = __ldg(gamma_e + c) * rsqrtf(__ldg(var_e + c) + EPSBN);
            sScl[c] = s;
            sShf[c] = __ldg(beta_e + c) - __ldg(mean_e + c) * s;
        }
    }

    float acc[2][8][4];
    float2 pi1[2][8], pi2[2][8];

    static const int chS[8]       = {0, 1, 2, 2, 3, 4, 5, 5};
    static const int chNewSlab[8] = {1, 1, 1, 0, 1, 1, 1, 0};
    static const int chSlabEnd[8] = {1, 1, 0, 1, 1, 1, 0, 1};

    #pragma unroll 1
    for (int i = 0; i < 8; i++) {
        CP_WAIT0();
        __syncthreads();

        int s = chS[i];
        int h = (i == 3 || i == 7) ? 1 : 0;
        bool isH1 = (s == 0 || s == 1 || s == 3 || s == 4);
        int hb = (s == 1 || s == 4) ? 128 : 0;

        if (chNewSlab[i]) {
            {
                float bz;
                if      (s == 0) bz = __ldg(b1a + tid)       + g_Pj_a[tb + tid];
                else if (s == 1) bz = __ldg(b1a + 128 + tid) + g_Pj_a[tb + 128 + tid];
                else if (s == 2) bz = __ldg(b2a + tid);
                else if (s == 3) bz = __ldg(b1m + tid)       + g_Pj_m[tb + tid];
                else if (s == 4) bz = __ldg(b1m + 128 + tid) + g_Pj_m[tb + 128 + tid];
                else             bz = __ldg(b2m + tid);
                sBias[tid] = bz;
            }
            #pragma unroll
            for (int mt = 0; mt < 2; mt++)
                #pragma unroll
                for (int nt = 0; nt < 8; nt++)
                    #pragma unroll
                    for (int z = 0; z < 4; z++) acc[mt][nt][z] = 0.f;
            if (isH1) {
                const float* Pi = (s < 2 ? g_Pi_a : g_Pi_m) + pib + hb;
                #pragma unroll
                for (int mt = 0; mt < 2; mt++) {
                    int r1 = row0 + m0 + mt * 16 + tq, r2 = r1 + 8;
                    #pragma unroll
                    for (int nt = 0; nt < 8; nt++) {
                        int cc = n0 + nt * 8 + tc;
                        pi1[mt][nt] = __ldg((const float2*)(Pi + (size_t)r1 * 256 + cc));
                        pi2[mt][nt] = __ldg((const float2*)(Pi + (size_t)r2 * 256 + cc));
                    }
                }
            }
        }

        if (s == 2 || s == 5)
            kloop<LDH>(sbase + OFF_H + (uint32_t)(h * 256), sbase + OFF_B,
                       m0, n0, aRow, aK, bRow, bK, acc);
        else
            kloop<LDAE>(sbase + OFF_A, sbase + OFF_B,
                        m0, n0, aRow, aK, bRow, bK, acc);

        __syncthreads();                // all reads of sB done
        if (i < 7) cp_chunk(sbase, i + 1, tid);   // refill (overlaps epilogue)

        if (!chSlabEnd[i]) continue;

        // ---------------- epilogue ----------------
        if (isH1) {
            #pragma unroll
            for (int mt = 0; mt < 2; mt++) {
                int r1 = m0 + mt * 16 + tq, r2 = r1 + 8;
                #pragma unroll
                for (int nt = 0; nt < 8; nt++) {
                    int cc = n0 + nt * 8 + tc;
                    float bz0 = sBias[cc], bz1 = sBias[cc + 1];
                    float a0 = fmaxf(acc[mt][nt][0] + pi1[mt][nt].x + bz0, 0.f);
                    float a1 = fmaxf(acc[mt][nt][1] + pi1[mt][nt].y + bz1, 0.f);
                    float a2 = fmaxf(acc[mt][nt][2] + pi2[mt][nt].x + bz0, 0.f);
                    float a3 = fmaxf(acc[mt][nt][3] + pi2[mt][nt].y + bz1, 0.f);
                    __half2 h0 = __floats2half2_rn(a0, a1);
                    __half2 h1 = __floats2half2_rn(a2, a3);
                    *(uint32_t*)(smc + OFF_H + (size_t)((r1 * LDH + hb + cc) << 1)) = *(uint32_t*)&h0;
                    *(uint32_t*)(smc + OFF_H + (size_t)((r2 * LDH + hb + cc) << 1)) = *(uint32_t*)&h1;
                }
            }
        } else if (s == 2) {
            float* go = edges_out + ((size_t)bb * 16384 + (size_t)p * 128 + row0) * 128;
            #pragma unroll
            for (int mt = 0; mt < 2; mt++) {
                int r1 = m0 + mt * 16 + tq, r2 = r1 + 8;
                float mk1 = sMask[r1], mk2 = sMask[r2];
                #pragma unroll
                for (int nt = 0; nt < 8; nt++) {
                    int cc = n0 + nt * 8 + tc;
                    float bz0 = sBias[cc], bz1 = sBias[cc + 1];
                    float v0 = fmaxf(acc[mt][nt][0] + bz0, 0.f) * mk1;
                    float v1 = fmaxf(acc[mt][nt][1] + bz1, 0.f) * mk1;
                    float v2 = fmaxf(acc[mt][nt][2] + bz0, 0.f) * mk2;
                    float v3 = fmaxf(acc[mt][nt][3] + bz1, 0.f) * mk2;
                    float s0 = sScl[cc], s1 = sScl[cc + 1];
                    float f0 = sShf[cc], f1 = sShf[cc + 1];
                    *(float2*)(go + (size_t)r1 * 128 + cc) = make_float2(v0 * s0 + f0, v1 * s1 + f1);
                    *(float2*)(go + (size_t)r2 * 128 + cc) = make_float2(v2 * s0 + f0, v3 * s1 + f1);
                    __half2 h0 = __floats2half2_rn(v0, v1);
                    __half2 h1 = __floats2half2_rn(v2, v3);
                    *(uint32_t*)(smc + OFF_A + (size_t)((r1 * LDAE + cc) << 1)) = *(uint32_t*)&h0;
                    *(uint32_t*)(smc + OFF_A + (size_t)((r2 * LDAE + cc) << 1)) = *(uint32_t*)&h1;
                }
            }
        } else {  // s == 5 : masked column sums over this CTA's 64 rows
            #pragma unroll
            for (int nt = 0; nt < 8; nt++) {
                int cc = n0 + nt * 8 + tc;
                float bz0 = sBias[cc], bz1 = sBias[cc + 1];
                float s0 = 0.f, s1 = 0.f;
                #pragma unroll
                for (int mt = 0; mt < 2; mt++) {
                    int r1 = m0 + mt * 16 + tq, r2 = r1 + 8;
                    float mk1 = sMask[r1], mk2 = sMask[r2];
                    s0 += fmaxf(acc[mt][nt][0] + bz0, 0.f) * mk1
                        + fmaxf(acc[mt][nt][2] + bz0, 0.f) * mk2;
                    s1 += fmaxf(acc[mt][nt][1] + bz1, 0.f) * mk1
                        + fmaxf(acc[mt][nt][3] + bz1, 0.f) * mk2;
                }
                #pragma unroll
                for (int d = 4; d < 32; d <<= 1) {
                    s0 += __shfl_xor_sync(0xffffffffu, s0, d);
                    s1 += __shfl_xor_sync(0xffffffffu, s1, d);
                }
                if (lane < 4) {
                    sRed[wm * 128 + cc]     = s0;
                    sRed[wm * 128 + cc + 1] = s1;
                }
            }
        }
    }
    __syncthreads();
    {
        float s = sRed[tid] + sRed[128 + tid];
        float* dst = half ? g_aggB : g_aggA;
        dst[(size_t)(bb * 128 + p) * 128 + tid] = s;
    }
}

// ---------------------------------------------------------------------------
// node update + BN : 512 blocks x 4 rows; agg = aggA + aggB
// ---------------------------------------------------------------------------
__global__ __launch_bounds__(256) void node_kernel(
    const float* __restrict__ W1u, const float* __restrict__ b1u,
    const float* __restrict__ W2u, const float* __restrict__ b2u,
    const float* __restrict__ gamma_n, const float* __restrict__ beta_n,
    const float* __restrict__ mean_n,  const float* __restrict__ var_n,
    float* __restrict__ nodes_out)
{
    __shared__ float sA[4 * 128];
    __shared__ float sH2[4 * 256];
    int row0 = blockIdx.x * 4;
    int tid = threadIdx.x;
    for (int i = tid; i < 512; i += 256)
        sA[i] = g_aggA[(size_t)row0 * 128 + i] + g_aggB[(size_t)row0 * 128 + i];
    __syncthreads();
    {
        float a[4];
        #pragma unroll
        for (int r = 0; r < 4; r++) a[r] = 0.f;
        const float* W = W1u + (size_t)128 * 256 + tid;
        #pragma unroll 4
        for (int kb = 0; kb < 128; kb += 4) {
            float w0 = W[(size_t)(kb + 0) * 256];
            float w1 = W[(size_t)(kb + 1) * 256];
            float w2 = W[(size_t)(kb + 2) * 256];
            float w3 = W[(size_t)(kb + 3) * 256];
            #pragma unroll
            for (int r = 0; r < 4; r++) {
                float4 xv = *(const float4*)(sA + r * 128 + kb);
                a[r] += xv.x * w0 + xv.y * w1 + xv.z * w2 + xv.w * w3;
            }
        }
        float bb1 = b1u[tid];
        #pragma unroll
        for (int r = 0; r < 4; r++) {
            float v = a[r] + g_Pu[(size_t)(row0 + r) * 256 + tid] + bb1;
            sH2[r * 256 + tid] = fmaxf(v, 0.f);
        }
    }
    __syncthreads();
    {
        int col = tid & 127;
        int rh  = tid >> 7;   // 0 or 1
        float c2[2] = {0.f, 0.f};
        const float* W2 = W2u + col;
        #pragma unroll 4
        for (int kb = 0; kb < 256; kb += 4) {
            float w0 = W2[(size_t)(kb + 0) * 128];
            float w1 = W2[(size_t)(kb + 1) * 128];
            float w2 = W2[(size_t)(kb + 2) * 128];
            float w3 = W2[(size_t)(kb + 3) * 128];
            #pragma unroll
            for (int rr = 0; rr < 2; rr++) {
                float4 hv = *(const float4*)(sH2 + (rh * 2 + rr) * 256 + kb);
                c2[rr] += hv.x * w0 + hv.y * w1 + hv.z * w2 + hv.w * w3;
            }
        }
        float bb2 = b2u[col];
        float s = gamma_n[col] * rsqrtf(var_n[col] + EPSBN);
        float sh = beta_n[col] - mean_n[col] * s;
        #pragma unroll
        for (int rr = 0; rr < 2; rr++) {
            float v = fmaxf(c2[rr] + bb2, 0.f);
            nodes_out[(size_t)(row0 + rh * 2 + rr) * 128 + col] = v * s + sh;
        }
    }
}

// ---------------------------------------------------------------------------
extern "C" void kernel_launch(void* const* d_in, const int* in_sizes, int n_in,
                              void* d_out, int out_size)
{
    const float* nodes = (const float*)d_in[0];
    const float* edges = (const float*)d_in[1];
    const float* mask  = (const float*)d_in[2];
    const float* W1a = (const float*)d_in[3];
    const float* b1a = (const float*)d_in[4];
    const float* W2a = (const float*)d_in[5];
    const float* b2a = (const float*)d_in[6];
    const float* W1m = (const float*)d_in[7];
    const float* b1m = (const float*)d_in[8];
    const float* W2m = (const float*)d_in[9];
    const float* b2m = (const float*)d_in[10];
    const float* W1u = (const float*)d_in[11];
    const float* b1u = (const float*)d_in[12];
    const float* W2u = (const float*)d_in[13];
    const float* b2u = (const float*)d_in[14];
    const float* gamma_n = (const float*)d_in[15];
    const float* beta_n  = (const float*)d_in[16];
    const float* mean_n  = (const float*)d_in[17];
    const float* var_n   = (const float*)d_in[18];
    const float* gamma_e = (const float*)d_in[19];
    const float* beta_e  = (const float*)d_in[20];
    const float* mean_e  = (const float*)d_in[21];
    const float* var_e   = (const float*)d_in[22];

    float* out = (float*)d_out;
    float* nodes_out = out;
    float* edges_out = out + (size_t)16 * 128 * 128;

    cudaFuncSetAttribute(edge_kernel, cudaFuncAttributeMaxDynamicSharedMemorySize,
                         (int)SMEM_EDGE_BYTES);

    prep_kernel<<<648, 256>>>(nodes, W1a, W2a, W1m, W2m, W1u);

    dim3 gridB(256, 16);
    edge_kernel<<<gridB, THREADS_EDGE, SMEM_EDGE_BYTES>>>(edges, mask,
                                                          b1a, b2a, b1m, b2m,
                                                          gamma_e, beta_e, mean_e, var_e,
                                                          edges_out);

    node_kernel<<<512, 256>>>(W1u, b1u, W2u, b2u,
                              gamma_n, beta_n, mean_n, var_n,
                              nodes_out);
}

// round 14
// speedup vs baseline: 1.0828x; 1.0828x over previous
#include <cuda_runtime.h>
#include <cuda_fp16.h>
#include <cstdint>
#include <math.h>

#define EPSBN 1e-3f

// ---------------- device scratch (no allocation allowed) ----------------
__device__ __align__(16) float  g_Pi_a[2048 * 256];
__device__ __align__(16) float  g_Pj_a[2048 * 256];
__device__ __align__(16) float  g_Pi_m[2048 * 256];
__device__ __align__(16) float  g_Pj_m[2048 * 256];
__device__ __align__(16) float  g_Pu [2048 * 256];
__device__ __align__(16) float  g_aggA[2048 * 128];   // partial agg, rows 0-63
__device__ __align__(16) float  g_aggB[2048 * 128];   // partial agg, rows 64-127
// slabs: g0/g1/g3/g4: [n=128][k=128]; g2/g5: [n=128][k=256]  (B[n][k]=W[k][n])
__device__ __align__(16) __half g_WT[131072];
__constant__ int c_OW[6] = {0, 16384, 32768, 65536, 81920, 98304};  // half offsets

// ---------------- PTX helpers (baseline sm_80+, safe for sm_103) --------
__device__ __forceinline__ uint32_t smem_u32(const void* p) {
    uint32_t a;
    asm("{ .reg .u64 t; cvta.to.shared.u64 t, %1; cvt.u32.u64 %0, t; }" : "=r"(a) : "l"(p));
    return a;
}
__device__ __forceinline__ void cp16(uint32_t s, const void* g) {
    asm volatile("cp.async.cg.shared.global [%0], [%1], 16;" :: "r"(s), "l"(g));
}
#define CP_COMMIT() asm volatile("cp.async.commit_group;" ::: "memory")
#define CP_WAIT0()  asm volatile("cp.async.wait_group 0;" ::: "memory")

__device__ __forceinline__ void ldsm4(uint32_t& r0, uint32_t& r1, uint32_t& r2, uint32_t& r3,
                                      uint32_t addr) {
    asm volatile("ldmatrix.sync.aligned.m8n8.x4.shared.b16 {%0,%1,%2,%3}, [%4];"
                 : "=r"(r0), "=r"(r1), "=r"(r2), "=r"(r3) : "r"(addr));
}
__device__ __forceinline__ void mma16816(float* c, const uint32_t* a, uint32_t b0, uint32_t b1) {
    asm volatile("mma.sync.aligned.m16n8k16.row.col.f32.f16.f16.f32 "
                 "{%0,%1,%2,%3},{%4,%5,%6,%7},{%8,%9},{%0,%1,%2,%3};"
                 : "+f"(c[0]), "+f"(c[1]), "+f"(c[2]), "+f"(c[3])
                 : "r"(a[0]), "r"(a[1]), "r"(a[2]), "r"(a[3]), "r"(b0), "r"(b1));
}

// ---------------- SMEM layout (bytes) ----------------
// sA: 64 x (128+8) f16 ; sH: 64 x (256+8) f16 ; sB: 128 n x (128+8) k f16
#define LDAE 136
#define LDH  264
#define OFF_A    0u         // 17408
#define OFF_H    17408u     // 33792
#define OFF_B    51200u     // 34816
#define OFF_BIAS 86016u     // 128 f32
#define OFF_MASK 86528u     // 64 f32
#define OFF_SCL  86784u     // 128 f32
#define OFF_SHF  87296u     // 128 f32
#define OFF_RED  87808u     // 2 x 128 f32
#define SMEM_EDGE_BYTES 88832u

// ---------------------------------------------------------------------------
// prep: blocks 0..1279 -> Pi_a/Pj_a/Pi_m/Pj_m/Pu (8 rows each) ;
//       blocks 1280..1287 -> g_WT
// ---------------------------------------------------------------------------
__global__ __launch_bounds__(256) void prep_kernel(
    const float* __restrict__ nodes,
    const float* __restrict__ W1a, const float* __restrict__ W2a,
    const float* __restrict__ W1m, const float* __restrict__ W2m,
    const float* __restrict__ W1u)
{
    int blk = blockIdx.x, tid = threadIdx.x;
    if (blk < 1280) {
        __shared__ float sX[1024];
        int m = blk >> 8, row0 = (blk & 255) * 8;
        for (int i = tid; i < 1024; i += 256) sX[i] = nodes[(size_t)row0 * 128 + i];
        __syncthreads();
        const float* W;
        float* O;
        switch (m) {
            case 0: W = W1a;             O = g_Pi_a; break;
            case 1: W = W1a + 128 * 256; O = g_Pj_a; break;
            case 2: W = W1m;             O = g_Pi_m; break;
            case 3: W = W1m + 128 * 256; O = g_Pj_m; break;
            default: W = W1u;            O = g_Pu;   break;
        }
        W += tid;
        O += (size_t)row0 * 256 + tid;
        float a[8];
        #pragma unroll
        for (int r = 0; r < 8; r++) a[r] = 0.f;
        #pragma unroll 4
        for (int kb = 0; kb < 128; kb += 4) {
            float w0 = W[(size_t)(kb + 0) * 256];
            float w1 = W[(size_t)(kb + 1) * 256];
            float w2 = W[(size_t)(kb + 2) * 256];
            float w3 = W[(size_t)(kb + 3) * 256];
            #pragma unroll
            for (int r = 0; r < 8; r++) {
                float4 xv = *(const float4*)(sX + r * 128 + kb);
                a[r] += xv.x * w0 + xv.y * w1 + xv.z * w2 + xv.w * w3;
            }
        }
        #pragma unroll
        for (int r = 0; r < 8; r++) O[(size_t)r * 256] = a[r];
        return;
    }
    int c = blk - 1280;  // 0..7
    int slab, nbase;
    if      (c == 0) { slab = 0; nbase = 0; }
    else if (c == 1) { slab = 1; nbase = 0; }
    else if (c <= 3) { slab = 2; nbase = (c - 2) * 64; }
    else if (c == 4) { slab = 3; nbase = 0; }
    else if (c == 5) { slab = 4; nbase = 0; }
    else             { slab = 5; nbase = (c - 6) * 64; }
    int K = (slab == 2 || slab == 5) ? 256 : 128;
    int nrows = (slab == 2 || slab == 5) ? 64 : 128;
    __half* dst = g_WT + c_OW[slab] + (size_t)nbase * K;
    for (int e = tid; e < nrows * K; e += 256) {
        int n = nbase + e / K;
        int k = e % K;
        float v;
        if      (slab == 0) v = W1a[(size_t)(256 + k) * 256 + n];
        else if (slab == 1) v = W1a[(size_t)(256 + k) * 256 + 128 + n];
        else if (slab == 2) v = W2a[(size_t)k * 128 + n];
        else if (slab == 3) v = W1m[(size_t)(256 + k) * 256 + n];
        else if (slab == 4) v = W1m[(size_t)(256 + k) * 256 + 128 + n];
        else                v = W2m[(size_t)k * 128 + n];
        dst[e] = __float2half_rn(v);
    }
}

// ---------------------------------------------------------------------------
// edge kernel: M=64 tile, 8 K=128 chunk phases, single B buffer, 2 CTAs/SM
// (exact R11 configuration, best measured: 428.5us total)
// chunk -> (slab, khalf): 0:(0,0) 1:(1,0) 2:(2,0) 3:(2,1) 4:(3,0) 5:(4,0) 6:(5,0) 7:(5,1)
// ---------------------------------------------------------------------------
__device__ __forceinline__ void cp_chunk(uint32_t sbase, int i, int tid) {
    static const int chS[8] = {0, 1, 2, 2, 3, 4, 5, 5};
    static const int chH[8] = {0, 0, 0, 1, 0, 0, 0, 1};
    int s = chS[i], h = chH[i];
    int K = (s == 2 || s == 5) ? 256 : 128;
    const __half* src = g_WT + c_OW[s] + h * 128;
    #pragma unroll
    for (int j = 0; j < 8; j++) {
        int f = tid + j * 256;
        int n = f >> 4, sub = f & 15;
        cp16(sbase + OFF_B + (uint32_t)(n * (LDAE * 2) + sub * 16),
             src + (size_t)n * K + sub * 8);
    }
    CP_COMMIT();
}

// 32x32 warp tile, K=128
template <int LDA_>
__device__ __forceinline__ void kloop(uint32_t aBase, uint32_t bBase,
                                      int m0, int n0, int aRow, int aK, int bRow, int bK,
                                      float (&acc)[2][4][4])
{
    #pragma unroll 4
    for (int kt = 0; kt < 8; kt++) {
        int kg = kt * 16;
        uint32_t a0[4], a1[4], bf[8];
        ldsm4(a0[0], a0[1], a0[2], a0[3],
              aBase + (uint32_t)(((m0 + aRow) * LDA_ + kg + aK) << 1));
        ldsm4(a1[0], a1[1], a1[2], a1[3],
              aBase + (uint32_t)(((m0 + 16 + aRow) * LDA_ + kg + aK) << 1));
        #pragma unroll
        for (int pp = 0; pp < 2; pp++)
            ldsm4(bf[pp * 4], bf[pp * 4 + 1], bf[pp * 4 + 2], bf[pp * 4 + 3],
                  bBase + (uint32_t)(((n0 + pp * 16 + bRow) * LDAE + kg + bK) << 1));
        #pragma unroll
        for (int nt = 0; nt < 4; nt++) {
            uint32_t bb0 = bf[(nt >> 1) * 4 + (nt & 1) * 2];
            uint32_t bb1 = bf[(nt >> 1) * 4 + (nt & 1) * 2 + 1];
            mma16816(acc[0][nt], a0, bb0, bb1);
            mma16816(acc[1][nt], a1, bb0, bb1);
        }
    }
}

__global__ __launch_bounds__(256, 2) void edge_kernel(
    const float* __restrict__ edges, const float* __restrict__ mask,
    const float* __restrict__ b1a, const float* __restrict__ b2a,
    const float* __restrict__ b1m, const float* __restrict__ b2m,
    const float* __restrict__ gamma_e, const float* __restrict__ beta_e,
    const float* __restrict__ mean_e,  const float* __restrict__ var_e,
    float* __restrict__ edges_out)
{
    extern __shared__ char smc[];
    uint32_t sbase = smem_u32(smc);
    int p = blockIdx.x >> 1, half = blockIdx.x & 1, bb = blockIdx.y;
    int tid = threadIdx.x, lane = tid & 31, w = tid >> 5;
    int wm = w >> 2, wn = w & 3;          // 2 x 4 warp grid, 32x32 tiles
    int m0 = wm * 32, n0 = wn * 32;

    float* sBias = (float*)(smc + OFF_BIAS);
    float* sMask = (float*)(smc + OFF_MASK);
    float* sScl  = (float*)(smc + OFF_SCL);
    float* sShf  = (float*)(smc + OFF_SHF);
    float* sRed  = (float*)(smc + OFF_RED);

    int aRow = lane & 15;
    int aK   = (lane & 16) ? 8 : 0;
    int bRow = (lane & 7) + ((lane & 16) ? 8 : 0);
    int bK   = (lane & 8) ? 8 : 0;
    int tq = lane >> 2;
    int tc = (lane & 3) * 2;

    cp_chunk(sbase, 0, tid);   // prefetch chunk 0 (overlaps E-tile load)

    const size_t tb   = (size_t)(bb * 128 + p) * 256;
    const size_t pib  = (size_t)bb * 128 * 256;
    const int    row0 = half * 64;                 // global row base of this CTA

    // ---- load E tile (64 rows, fp16) + consts
    {
        const float4* Eg = (const float4*)(edges +
            (size_t)(bb * 16384 + p * 128 + row0) * 128);
        #pragma unroll 4
        for (int i = tid; i < 2048; i += 256) {
            int qq = i >> 5, k4 = (i & 31) << 2;
            float4 e = __ldg(Eg + i);
            __half2 e0 = __floats2half2_rn(e.x, e.y), e1 = __floats2half2_rn(e.z, e.w);
            *(uint2*)(smc + OFF_A + (size_t)((qq * LDAE + k4) << 1)) =
                make_uint2(*(uint32_t*)&e0, *(uint32_t*)&e1);
        }
        if (tid < 64)
            sMask[tid] = __ldg(mask + (size_t)bb * 16384 + p * 128 + row0 + tid);
        if (tid >= 128 && tid < 256) {
            int c = tid - 128;
            float s = __ldg(gamma_e + c) * rsqrtf(__ldg(var_e + c) + EPSBN);
            sScl[c] = s;
            sShf[c] = __ldg(beta_e + c) - __ldg(mean_e + c) * s;
        }
    }

    float acc[2][4][4];
    float2 pi1[2][4], pi2[2][4];

    static const int chS[8]       = {0, 1, 2, 2, 3, 4, 5, 5};
    static const int chNewSlab[8] = {1, 1, 1, 0, 1, 1, 1, 0};
    static const int chSlabEnd[8] = {1, 1, 0, 1, 1, 1, 0, 1};

    #pragma unroll 1
    for (int i = 0; i < 8; i++) {
        CP_WAIT0();
        __syncthreads();

        int s = chS[i];
        int h = (i == 3 || i == 7) ? 1 : 0;
        bool isH1 = (s == 0 || s == 1 || s == 3 || s == 4);
        int hb = (s == 1 || s == 4) ? 128 : 0;

        if (chNewSlab[i]) {
            if (tid < 128) {
                float bz;
                if      (s == 0) bz = __ldg(b1a + tid)       + g_Pj_a[tb + tid];
                else if (s == 1) bz = __ldg(b1a + 128 + tid) + g_Pj_a[tb + 128 + tid];
                else if (s == 2) bz = __ldg(b2a + tid);
                else if (s == 3) bz = __ldg(b1m + tid)       + g_Pj_m[tb + tid];
                else if (s == 4) bz = __ldg(b1m + 128 + tid) + g_Pj_m[tb + 128 + tid];
                else             bz = __ldg(b2m + tid);
                sBias[tid] = bz;
            }
            #pragma unroll
            for (int mt = 0; mt < 2; mt++)
                #pragma unroll
                for (int nt = 0; nt < 4; nt++)
                    #pragma unroll
                    for (int z = 0; z < 4; z++) acc[mt][nt][z] = 0.f;
            if (isH1) {
                const float* Pi = (s < 2 ? g_Pi_a : g_Pi_m) + pib + hb;
                #pragma unroll
                for (int mt = 0; mt < 2; mt++) {
                    int r1 = row0 + m0 + mt * 16 + tq, r2 = r1 + 8;
                    #pragma unroll
                    for (int nt = 0; nt < 4; nt++) {
                        int cc = n0 + nt * 8 + tc;
                        pi1[mt][nt] = __ldg((const float2*)(Pi + (size_t)r1 * 256 + cc));
                        pi2[mt][nt] = __ldg((const float2*)(Pi + (size_t)r2 * 256 + cc));
                    }
                }
            }
        }

        if (s == 2 || s == 5)
            kloop<LDH>(sbase + OFF_H + (uint32_t)(h * 256), sbase + OFF_B,
                       m0, n0, aRow, aK, bRow, bK, acc);
        else
            kloop<LDAE>(sbase + OFF_A, sbase + OFF_B,
                        m0, n0, aRow, aK, bRow, bK, acc);

        __syncthreads();                // all reads of sB done
        if (i < 7) cp_chunk(sbase, i + 1, tid);   // refill (overlaps epilogue)

        if (!chSlabEnd[i]) continue;

        // ---------------- epilogue ----------------
        if (isH1) {
            #pragma unroll
            for (int mt = 0; mt < 2; mt++) {
                int r1 = m0 + mt * 16 + tq, r2 = r1 + 8;
                #pragma unroll
                for (int nt = 0; nt < 4; nt++) {
                    int cc = n0 + nt * 8 + tc;
                    float bz0 = sBias[cc], bz1 = sBias[cc + 1];
                    float a0 = fmaxf(acc[mt][nt][0] + pi1[mt][nt].x + bz0, 0.f);
                    float a1 = fmaxf(acc[mt][nt][1] + pi1[mt][nt].y + bz1, 0.f);
                    float a2 = fmaxf(acc[mt][nt][2] + pi2[mt][nt].x + bz0, 0.f);
                    float a3 = fmaxf(acc[mt][nt][3] + pi2[mt][nt].y + bz1, 0.f);
                    __half2 h0 = __floats2half2_rn(a0, a1);
                    __half2 h1 = __floats2half2_rn(a2, a3);
                    *(uint32_t*)(smc + OFF_H + (size_t)((r1 * LDH + hb + cc) << 1)) = *(uint32_t*)&h0;
                    *(uint32_t*)(smc + OFF_H + (size_t)((r2 * LDH + hb + cc) << 1)) = *(uint32_t*)&h1;
                }
            }
        } else if (s == 2) {
            float* go = edges_out + ((size_t)bb * 16384 + (size_t)p * 128 + row0) * 128;
            #pragma unroll
            for (int mt = 0; mt < 2; mt++) {
                int r1 = m0 + mt * 16 + tq, r2 = r1 + 8;
                float mk1 = sMask[r1], mk2 = sMask[r2];
                #pragma unroll
                for (int nt = 0; nt < 4; nt++) {
                    int cc = n0 + nt * 8 + tc;
                    float bz0 = sBias[cc], bz1 = sBias[cc + 1];
                    float v0 = fmaxf(acc[mt][nt][0] + bz0, 0.f) * mk1;
                    float v1 = fmaxf(acc[mt][nt][1] + bz1, 0.f) * mk1;
                    float v2 = fmaxf(acc[mt][nt][2] + bz0, 0.f) * mk2;
                    float v3 = fmaxf(acc[mt][nt][3] + bz1, 0.f) * mk2;
                    float s0 = sScl[cc], s1 = sScl[cc + 1];
                    float f0 = sShf[cc], f1 = sShf[cc + 1];
                    *(float2*)(go + (size_t)r1 * 128 + cc) = make_float2(v0 * s0 + f0, v1 * s1 + f1);
                    *(float2*)(go + (size_t)r2 * 128 + cc) = make_float2(v2 * s0 + f0, v3 * s1 + f1);
                    __half2 h0 = __floats2half2_rn(v0, v1);
                    __half2 h1 = __floats2half2_rn(v2, v3);
                    *(uint32_t*)(smc + OFF_A + (size_t)((r1 * LDAE + cc) << 1)) = *(uint32_t*)&h0;
                    *(uint32_t*)(smc + OFF_A + (size_t)((r2 * LDAE + cc) << 1)) = *(uint32_t*)&h1;
                }
            }
        } else {  // s == 5 : masked column sums over this CTA's 64 rows
            #pragma unroll
            for (int nt = 0; nt < 4; nt++) {
                int cc = n0 + nt * 8 + tc;
                float bz0 = sBias[cc], bz1 = sBias[cc + 1];
                float s0 = 0.f, s1 = 0.f;
                #pragma unroll
                for (int mt = 0; mt < 2; mt++) {
                    int r1 = m0 + mt * 16 + tq, r2 = r1 + 8;
                    float mk1 = sMask[r1], mk2 = sMask[r2];
                    s0 += fmaxf(acc[mt][nt][0] + bz0, 0.f) * mk1
                        + fmaxf(acc[mt][nt][2] + bz0, 0.f) * mk2;
                    s1 += fmaxf(acc[mt][nt][1] + bz1, 0.f) * mk1
                        + fmaxf(acc[mt][nt][3] + bz1, 0.f) * mk2;
                }
                #pragma unroll
                for (int d = 4; d < 32; d <<= 1) {
                    s0 += __shfl_xor_sync(0xffffffffu, s0, d);
                    s1 += __shfl_xor_sync(0xffffffffu, s1, d);
                }
                if (lane < 4) {
                    sRed[wm * 128 + cc]     = s0;
                    sRed[wm * 128 + cc + 1] = s1;
                }
            }
        }
    }
    __syncthreads();
    if (tid < 128) {
        float s = sRed[tid] + sRed[128 + tid];
        float* dst = half ? g_aggB : g_aggA;
        dst[(size_t)(bb * 128 + p) * 128 + tid] = s;
    }
}

// ---------------------------------------------------------------------------
// node update + BN : 512 blocks x 4 rows; agg = aggA + aggB
// ---------------------------------------------------------------------------
__global__ __launch_bounds__(256) void node_kernel(
    const float* __restrict__ W1u, const float* __restrict__ b1u,
    const float* __restrict__ W2u, const float* __restrict__ b2u,
    const float* __restrict__ gamma_n, const float* __restrict__ beta_n,
    const float* __restrict__ mean_n,  const float* __restrict__ var_n,
    float* __restrict__ nodes_out)
{
    __shared__ float sA[4 * 128];
    __shared__ float sH2[4 * 256];
    int row0 = blockIdx.x * 4;
    int tid = threadIdx.x;
    for (int i = tid; i < 512; i += 256)
        sA[i] = g_aggA[(size_t)row0 * 128 + i] + g_aggB[(size_t)row0 * 128 + i];
    __syncthreads();
    {
        float a[4];
        #pragma unroll
        for (int r = 0; r < 4; r++) a[r] = 0.f;
        const float* W = W1u + (size_t)128 * 256 + tid;
        #pragma unroll 4
        for (int kb = 0; kb < 128; kb += 4) {
            float w0 = W[(size_t)(kb + 0) * 256];
            float w1 = W[(size_t)(kb + 1) * 256];
            float w2 = W[(size_t)(kb + 2) * 256];
            float w3 = W[(size_t)(kb + 3) * 256];
            #pragma unroll
            for (int r = 0; r < 4; r++) {
                float4 xv = *(const float4*)(sA + r * 128 + kb);
                a[r] += xv.x * w0 + xv.y * w1 + xv.z * w2 + xv.w * w3;
            }
        }
        float bb1 = b1u[tid];
        #pragma unroll
        for (int r = 0; r < 4; r++) {
            float v = a[r] + g_Pu[(size_t)(row0 + r) * 256 + tid] + bb1;
            sH2[r * 256 + tid] = fmaxf(v, 0.f);
        }
    }
    __syncthreads();
    {
        int col = tid & 127;
        int rh  = tid >> 7;   // 0 or 1
        float c2[2] = {0.f, 0.f};
        const float* W2 = W2u + col;
        #pragma unroll 4
        for (int kb = 0; kb < 256; kb += 4) {
            float w0 = W2[(size_t)(kb + 0) * 128];
            float w1 = W2[(size_t)(kb + 1) * 128];
            float w2 = W2[(size_t)(kb + 2) * 128];
            float w3 = W2[(size_t)(kb + 3) * 128];
            #pragma unroll
            for (int rr = 0; rr < 2; rr++) {
                float4 hv = *(const float4*)(sH2 + (rh * 2 + rr) * 256 + kb);
                c2[rr] += hv.x * w0 + hv.y * w1 + hv.z * w2 + hv.w * w3;
            }
        }
        float bb2 = b2u[col];
        float s = gamma_n[col] * rsqrtf(var_n[col] + EPSBN);
        float sh = beta_n[col] - mean_n[col] * s;
        #pragma unroll
        for (int rr = 0; rr < 2; rr++) {
            float v = fmaxf(c2[rr] + bb2, 0.f);
            nodes_out[(size_t)(row0 + rh * 2 + rr) * 128 + col] = v * s + sh;
        }
    }
}

// ---------------------------------------------------------------------------
extern "C" void kernel_launch(void* const* d_in, const int* in_sizes, int n_in,
                              void* d_out, int out_size)
{
    const float* nodes = (const float*)d_in[0];
    const float* edges = (const float*)d_in[1];
    const float* mask  = (const float*)d_in[2];
    const float* W1a = (const float*)d_in[3];
    const float* b1a = (const float*)d_in[4];
    const float* W2a = (const float*)d_in[5];
    const float* b2a = (const float*)d_in[6];
    const float* W1m = (const float*)d_in[7];
    const float* b1m = (const float*)d_in[8];
    const float* W2m = (const float*)d_in[9];
    const float* b2m = (const float*)d_in[10];
    const float* W1u = (const float*)d_in[11];
    const float* b1u = (const float*)d_in[12];
    const float* W2u = (const float*)d_in[13];
    const float* b2u = (const float*)d_in[14];
    const float* gamma_n = (const float*)d_in[15];
    const float* beta_n  = (const float*)d_in[16];
    const float* mean_n  = (const float*)d_in[17];
    const float* var_n   = (const float*)d_in[18];
    const float* gamma_e = (const float*)d_in[19];
    const float* beta_e  = (const float*)d_in[20];
    const float* mean_e  = (const float*)d_in[21];
    const float* var_e   = (const float*)d_in[22];

    float* out = (float*)d_out;
    float* nodes_out = out;
    float* edges_out = out + (size_t)16 * 128 * 128;

    cudaFuncSetAttribute(edge_kernel, cudaFuncAttributeMaxDynamicSharedMemorySize,
                         (int)SMEM_EDGE_BYTES);

    prep_kernel<<<1288, 256>>>(nodes, W1a, W2a, W1m, W2m, W1u);

    dim3 gridB(256, 16);
    edge_kernel<<<gridB, 256, SMEM_EDGE_BYTES>>>(edges, mask,
                                                 b1a, b2a, b1m, b2m,
                                                 gamma_e, beta_e, mean_e, var_e,
                                                 edges_out);

    node_kernel<<<512, 256>>>(W1u, b1u, W2u, b2u,
                              gamma_n, beta_n, mean_n, var_n,
                              nodes_out);
}

// round 15
// speedup vs baseline: 1.1011x; 1.0170x over previous
#include <cuda_runtime.h>
#include <cuda_fp16.h>
#include <cstdint>
#include <math.h>

#define EPSBN 1e-3f

// ---------------- device scratch (no allocation allowed) ----------------
__device__ __align__(16) float  g_Pi_a[2048 * 256];
__device__ __align__(16) float  g_Pj_a[2048 * 256];
__device__ __align__(16) float  g_Pi_m[2048 * 256];
__device__ __align__(16) float  g_Pj_m[2048 * 256];
__device__ __align__(16) float  g_Pu [2048 * 256];
__device__ __align__(16) float  g_aggA[2048 * 128];   // partial agg, rows 0-63
__device__ __align__(16) float  g_aggB[2048 * 128];   // partial agg, rows 64-127
// slabs: g0/g1/g3/g4: [n=128][k=128]; g2/g5: [n=128][k=256]  (B[n][k]=W[k][n])
__device__ __align__(16) __half g_WT[131072];
__constant__ int c_OW[6] = {0, 16384, 32768, 65536, 81920, 98304};  // half offsets

// ---------------- PTX helpers (baseline sm_80+, safe for sm_103) --------
__device__ __forceinline__ uint32_t smem_u32(const void* p) {
    uint32_t a;
    asm("{ .reg .u64 t; cvta.to.shared.u64 t, %1; cvt.u32.u64 %0, t; }" : "=r"(a) : "l"(p));
    return a;
}
__device__ __forceinline__ void cp16(uint32_t s, const void* g) {
    asm volatile("cp.async.cg.shared.global [%0], [%1], 16;" :: "r"(s), "l"(g));
}
#define CP_COMMIT() asm volatile("cp.async.commit_group;" ::: "memory")
#define CP_WAIT0()  asm volatile("cp.async.wait_group 0;" ::: "memory")

__device__ __forceinline__ void ldsm4(uint32_t& r0, uint32_t& r1, uint32_t& r2, uint32_t& r3,
                                      uint32_t addr) {
    asm volatile("ldmatrix.sync.aligned.m8n8.x4.shared.b16 {%0,%1,%2,%3}, [%4];"
                 : "=r"(r0), "=r"(r1), "=r"(r2), "=r"(r3) : "r"(addr));
}
__device__ __forceinline__ void mma16816(float* c, const uint32_t* a, uint32_t b0, uint32_t b1) {
    asm volatile("mma.sync.aligned.m16n8k16.row.col.f32.f16.f16.f32 "
                 "{%0,%1,%2,%3},{%4,%5,%6,%7},{%8,%9},{%0,%1,%2,%3};"
                 : "+f"(c[0]), "+f"(c[1]), "+f"(c[2]), "+f"(c[3])
                 : "r"(a[0]), "r"(a[1]), "r"(a[2]), "r"(a[3]), "r"(b0), "r"(b1));
}

// ---------------- SMEM layout (bytes) ----------------
// sA: 64 x (128+8) f16 ; sH: 64 x (256+8) f16 ; sB: 128 n x (128+8) k f16
#define LDAE 136
#define LDH  264
#define OFF_A    0u         // 17408
#define OFF_H    17408u     // 33792
#define OFF_B    51200u     // 34816
#define OFF_BIAS 86016u     // 128 f32
#define OFF_MASK 86528u     // 64 f32
#define OFF_SCL  86784u     // 128 f32
#define OFF_SHF  87296u     // 128 f32
#define OFF_RED  87808u     // 2 x 128 f32
#define SMEM_EDGE_BYTES 88832u

// ---------------------------------------------------------------------------
// prep: blocks 0..639 -> Pi_a/Pj_a/Pi_m/Pj_m/Pu (16 rows each) ;
//       blocks 640..647 -> g_WT
// ---------------------------------------------------------------------------
__global__ __launch_bounds__(256) void prep_kernel(
    const float* __restrict__ nodes,
    const float* __restrict__ W1a, const float* __restrict__ W2a,
    const float* __restrict__ W1m, const float* __restrict__ W2m,
    const float* __restrict__ W1u)
{
    int blk = blockIdx.x, tid = threadIdx.x;
    if (blk < 640) {
        __shared__ float sX[2048];
        int m = blk >> 7, row0 = (blk & 127) * 16;
        for (int i = tid; i < 2048; i += 256) sX[i] = nodes[(size_t)row0 * 128 + i];
        __syncthreads();
        const float* W;
        float* O;
        switch (m) {
            case 0: W = W1a;             O = g_Pi_a; break;
            case 1: W = W1a + 128 * 256; O = g_Pj_a; break;
            case 2: W = W1m;             O = g_Pi_m; break;
            case 3: W = W1m + 128 * 256; O = g_Pj_m; break;
            default: W = W1u;            O = g_Pu;   break;
        }
        W += tid;
        O += (size_t)row0 * 256 + tid;
        float a[16];
        #pragma unroll
        for (int r = 0; r < 16; r++) a[r] = 0.f;
        #pragma unroll 4
        for (int kb = 0; kb < 128; kb += 4) {
            float w0 = W[(size_t)(kb + 0) * 256];
            float w1 = W[(size_t)(kb + 1) * 256];
            float w2 = W[(size_t)(kb + 2) * 256];
            float w3 = W[(size_t)(kb + 3) * 256];
            #pragma unroll
            for (int r = 0; r < 16; r++) {
                float4 xv = *(const float4*)(sX + r * 128 + kb);
                a[r] += xv.x * w0 + xv.y * w1 + xv.z * w2 + xv.w * w3;
            }
        }
        #pragma unroll
        for (int r = 0; r < 16; r++) O[(size_t)r * 256] = a[r];
        return;
    }
    int c = blk - 640;  // 0..7
    int slab, nbase;
    if      (c == 0) { slab = 0; nbase = 0; }
    else if (c == 1) { slab = 1; nbase = 0; }
    else if (c <= 3) { slab = 2; nbase = (c - 2) * 64; }
    else if (c == 4) { slab = 3; nbase = 0; }
    else if (c == 5) { slab = 4; nbase = 0; }
    else             { slab = 5; nbase = (c - 6) * 64; }
    int K = (slab == 2 || slab == 5) ? 256 : 128;
    int nrows = (slab == 2 || slab == 5) ? 64 : 128;
    __half* dst = g_WT + c_OW[slab] + (size_t)nbase * K;
    for (int e = tid; e < nrows * K; e += 256) {
        int n = nbase + e / K;
        int k = e % K;
        float v;
        if      (slab == 0) v = W1a[(size_t)(256 + k) * 256 + n];
        else if (slab == 1) v = W1a[(size_t)(256 + k) * 256 + 128 + n];
        else if (slab == 2) v = W2a[(size_t)k * 128 + n];
        else if (slab == 3) v = W1m[(size_t)(256 + k) * 256 + n];
        else if (slab == 4) v = W1m[(size_t)(256 + k) * 256 + 128 + n];
        else                v = W2m[(size_t)k * 128 + n];
        dst[e] = __float2half_rn(v);
    }
}

// ---------------------------------------------------------------------------
// edge kernel: M=64 tile, 8 K=128 chunk phases, single B buffer, 2 CTAs/SM
// (exact R11 configuration, best measured: 428.5us total)
// chunk -> (slab, khalf): 0:(0,0) 1:(1,0) 2:(2,0) 3:(2,1) 4:(3,0) 5:(4,0) 6:(5,0) 7:(5,1)
// ---------------------------------------------------------------------------
__device__ __forceinline__ void cp_chunk(uint32_t sbase, int i, int tid) {
    static const int chS[8] = {0, 1, 2, 2, 3, 4, 5, 5};
    static const int chH[8] = {0, 0, 0, 1, 0, 0, 0, 1};
    int s = chS[i], h = chH[i];
    int K = (s == 2 || s == 5) ? 256 : 128;
    const __half* src = g_WT + c_OW[s] + h * 128;
    #pragma unroll
    for (int j = 0; j < 8; j++) {
        int f = tid + j * 256;
        int n = f >> 4, sub = f & 15;
        cp16(sbase + OFF_B + (uint32_t)(n * (LDAE * 2) + sub * 16),
             src + (size_t)n * K + sub * 8);
    }
    CP_COMMIT();
}

// 32x32 warp tile, K=128
template <int LDA_>
__device__ __forceinline__ void kloop(uint32_t aBase, uint32_t bBase,
                                      int m0, int n0, int aRow, int aK, int bRow, int bK,
                                      float (&acc)[2][4][4])
{
    #pragma unroll 4
    for (int kt = 0; kt < 8; kt++) {
        int kg = kt * 16;
        uint32_t a0[4], a1[4], bf[8];
        ldsm4(a0[0], a0[1], a0[2], a0[3],
              aBase + (uint32_t)(((m0 + aRow) * LDA_ + kg + aK) << 1));
        ldsm4(a1[0], a1[1], a1[2], a1[3],
              aBase + (uint32_t)(((m0 + 16 + aRow) * LDA_ + kg + aK) << 1));
        #pragma unroll
        for (int pp = 0; pp < 2; pp++)
            ldsm4(bf[pp * 4], bf[pp * 4 + 1], bf[pp * 4 + 2], bf[pp * 4 + 3],
                  bBase + (uint32_t)(((n0 + pp * 16 + bRow) * LDAE + kg + bK) << 1));
        #pragma unroll
        for (int nt = 0; nt < 4; nt++) {
            uint32_t bb0 = bf[(nt >> 1) * 4 + (nt & 1) * 2];
            uint32_t bb1 = bf[(nt >> 1) * 4 + (nt & 1) * 2 + 1];
            mma16816(acc[0][nt], a0, bb0, bb1);
            mma16816(acc[1][nt], a1, bb0, bb1);
        }
    }
}

__global__ __launch_bounds__(256, 2) void edge_kernel(
    const float* __restrict__ edges, const float* __restrict__ mask,
    const float* __restrict__ b1a, const float* __restrict__ b2a,
    const float* __restrict__ b1m, const float* __restrict__ b2m,
    const float* __restrict__ gamma_e, const float* __restrict__ beta_e,
    const float* __restrict__ mean_e,  const float* __restrict__ var_e,
    float* __restrict__ edges_out)
{
    extern __shared__ char smc[];
    uint32_t sbase = smem_u32(smc);
    int p = blockIdx.x >> 1, half = blockIdx.x & 1, bb = blockIdx.y;
    int tid = threadIdx.x, lane = tid & 31, w = tid >> 5;
    int wm = w >> 2, wn = w & 3;          // 2 x 4 warp grid, 32x32 tiles
    int m0 = wm * 32, n0 = wn * 32;

    float* sBias = (float*)(smc + OFF_BIAS);
    float* sMask = (float*)(smc + OFF_MASK);
    float* sScl  = (float*)(smc + OFF_SCL);
    float* sShf  = (float*)(smc + OFF_SHF);
    float* sRed  = (float*)(smc + OFF_RED);

    int aRow = lane & 15;
    int aK   = (lane & 16) ? 8 : 0;
    int bRow = (lane & 7) + ((lane & 16) ? 8 : 0);
    int bK   = (lane & 8) ? 8 : 0;
    int tq = lane >> 2;
    int tc = (lane & 3) * 2;

    cp_chunk(sbase, 0, tid);   // prefetch chunk 0 (overlaps E-tile load)

    const size_t tb   = (size_t)(bb * 128 + p) * 256;
    const size_t pib  = (size_t)bb * 128 * 256;
    const int    row0 = half * 64;                 // global row base of this CTA

    // ---- load E tile (64 rows, fp16) + consts
    {
        const float4* Eg = (const float4*)(edges +
            (size_t)(bb * 16384 + p * 128 + row0) * 128);
        #pragma unroll 4
        for (int i = tid; i < 2048; i += 256) {
            int qq = i >> 5, k4 = (i & 31) << 2;
            float4 e = __ldg(Eg + i);
            __half2 e0 = __floats2half2_rn(e.x, e.y), e1 = __floats2half2_rn(e.z, e.w);
            *(uint2*)(smc + OFF_A + (size_t)((qq * LDAE + k4) << 1)) =
                make_uint2(*(uint32_t*)&e0, *(uint32_t*)&e1);
        }
        if (tid < 64)
            sMask[tid] = __ldg(mask + (size_t)bb * 16384 + p * 128 + row0 + tid);
        if (tid >= 128 && tid < 256) {
            int c = tid - 128;
            float s = __ldg(gamma_e + c) * rsqrtf(__ldg(var_e + c) + EPSBN);
            sScl[c] = s;
            sShf[c] = __ldg(beta_e + c) - __ldg(mean_e + c) * s;
        }
    }

    float acc[2][4][4];
    float2 pi1[2][4], pi2[2][4];

    static const int chS[8]       = {0, 1, 2, 2, 3, 4, 5, 5};
    static const int chNewSlab[8] = {1, 1, 1, 0, 1, 1, 1, 0};
    static const int chSlabEnd[8] = {1, 1, 0, 1, 1, 1, 0, 1};

    #pragma unroll 1
    for (int i = 0; i < 8; i++) {
        CP_WAIT0();
        __syncthreads();

        int s = chS[i];
        int h = (i == 3 || i == 7) ? 1 : 0;
        bool isH1 = (s == 0 || s == 1 || s == 3 || s == 4);
        int hb = (s == 1 || s == 4) ? 128 : 0;

        if (chNewSlab[i]) {
            if (tid < 128) {
                float bz;
                if      (s == 0) bz = __ldg(b1a + tid)       + g_Pj_a[tb + tid];
                else if (s == 1) bz = __ldg(b1a + 128 + tid) + g_Pj_a[tb + 128 + tid];
                else if (s == 2) bz = __ldg(b2a + tid);
                else if (s == 3) bz = __ldg(b1m + tid)       + g_Pj_m[tb + tid];
                else if (s == 4) bz = __ldg(b1m + 128 + tid) + g_Pj_m[tb + 128 + tid];
                else             bz = __ldg(b2m + tid);
                sBias[tid] = bz;
            }
            #pragma unroll
            for (int mt = 0; mt < 2; mt++)
                #pragma unroll
                for (int nt = 0; nt < 4; nt++)
                    #pragma unroll
                    for (int z = 0; z < 4; z++) acc[mt][nt][z] = 0.f;
            if (isH1) {
                const float* Pi = (s < 2 ? g_Pi_a : g_Pi_m) + pib + hb;
                #pragma unroll
                for (int mt = 0; mt < 2; mt++) {
                    int r1 = row0 + m0 + mt * 16 + tq, r2 = r1 + 8;
                    #pragma unroll
                    for (int nt = 0; nt < 4; nt++) {
                        int cc = n0 + nt * 8 + tc;
                        pi1[mt][nt] = __ldg((const float2*)(Pi + (size_t)r1 * 256 + cc));
                        pi2[mt][nt] = __ldg((const float2*)(Pi + (size_t)r2 * 256 + cc));
                    }
                }
            }
        }

        if (s == 2 || s == 5)
            kloop<LDH>(sbase + OFF_H + (uint32_t)(h * 256), sbase + OFF_B,
                       m0, n0, aRow, aK, bRow, bK, acc);
        else
            kloop<LDAE>(sbase + OFF_A, sbase + OFF_B,
                        m0, n0, aRow, aK, bRow, bK, acc);

        __syncthreads();                // all reads of sB done
        if (i < 7) cp_chunk(sbase, i + 1, tid);   // refill (overlaps epilogue)

        if (!chSlabEnd[i]) continue;

        // ---------------- epilogue ----------------
        if (isH1) {
            #pragma unroll
            for (int mt = 0; mt < 2; mt++) {
                int r1 = m0 + mt * 16 + tq, r2 = r1 + 8;
                #pragma unroll
                for (int nt = 0; nt < 4; nt++) {
                    int cc = n0 + nt * 8 + tc;
                    float bz0 = sBias[cc], bz1 = sBias[cc + 1];
                    float a0 = fmaxf(acc[mt][nt][0] + pi1[mt][nt].x + bz0, 0.f);
                    float a1 = fmaxf(acc[mt][nt][1] + pi1[mt][nt].y + bz1, 0.f);
                    float a2 = fmaxf(acc[mt][nt][2] + pi2[mt][nt].x + bz0, 0.f);
                    float a3 = fmaxf(acc[mt][nt][3] + pi2[mt][nt].y + bz1, 0.f);
                    __half2 h0 = __floats2half2_rn(a0, a1);
                    __half2 h1 = __floats2half2_rn(a2, a3);
                    *(uint32_t*)(smc + OFF_H + (size_t)((r1 * LDH + hb + cc) << 1)) = *(uint32_t*)&h0;
                    *(uint32_t*)(smc + OFF_H + (size_t)((r2 * LDH + hb + cc) << 1)) = *(uint32_t*)&h1;
                }
            }
        } else if (s == 2) {
            float* go = edges_out + ((size_t)bb * 16384 + (size_t)p * 128 + row0) * 128;
            #pragma unroll
            for (int mt = 0; mt < 2; mt++) {
                int r1 = m0 + mt * 16 + tq, r2 = r1 + 8;
                float mk1 = sMask[r1], mk2 = sMask[r2];
                #pragma unroll
                for (int nt = 0; nt < 4; nt++) {
                    int cc = n0 + nt * 8 + tc;
                    float bz0 = sBias[cc], bz1 = sBias[cc + 1];
                    float v0 = fmaxf(acc[mt][nt][0] + bz0, 0.f) * mk1;
                    float v1 = fmaxf(acc[mt][nt][1] + bz1, 0.f) * mk1;
                    float v2 = fmaxf(acc[mt][nt][2] + bz0, 0.f) * mk2;
                    float v3 = fmaxf(acc[mt][nt][3] + bz1, 0.f) * mk2;
                    float s0 = sScl[cc], s1 = sScl[cc + 1];
                    float f0 = sShf[cc], f1 = sShf[cc + 1];
                    *(float2*)(go + (size_t)r1 * 128 + cc) = make_float2(v0 * s0 + f0, v1 * s1 + f1);
                    *(float2*)(go + (size_t)r2 * 128 + cc) = make_float2(v2 * s0 + f0, v3 * s1 + f1);
                    __half2 h0 = __floats2half2_rn(v0, v1);
                    __half2 h1 = __floats2half2_rn(v2, v3);
                    *(uint32_t*)(smc + OFF_A + (size_t)((r1 * LDAE + cc) << 1)) = *(uint32_t*)&h0;
                    *(uint32_t*)(smc + OFF_A + (size_t)((r2 * LDAE + cc) << 1)) = *(uint32_t*)&h1;
                }
            }
        } else {  // s == 5 : masked column sums over this CTA's 64 rows
            #pragma unroll
            for (int nt = 0; nt < 4; nt++) {
                int cc = n0 + nt * 8 + tc;
                float bz0 = sBias[cc], bz1 = sBias[cc + 1];
                float s0 = 0.f, s1 = 0.f;
                #pragma unroll
                for (int mt = 0; mt < 2; mt++) {
                    int r1 = m0 + mt * 16 + tq, r2 = r1 + 8;
                    float mk1 = sMask[r1], mk2 = sMask[r2];
                    s0 += fmaxf(acc[mt][nt][0] + bz0, 0.f) * mk1
                        + fmaxf(acc[mt][nt][2] + bz0, 0.f) * mk2;
                    s1 += fmaxf(acc[mt][nt][1] + bz1, 0.f) * mk1
                        + fmaxf(acc[mt][nt][3] + bz1, 0.f) * mk2;
                }
                #pragma unroll
                for (int d = 4; d < 32; d <<= 1) {
                    s0 += __shfl_xor_sync(0xffffffffu, s0, d);
                    s1 += __shfl_xor_sync(0xffffffffu, s1, d);
                }
                if (lane < 4) {
                    sRed[wm * 128 + cc]     = s0;
                    sRed[wm * 128 + cc + 1] = s1;
                }
            }
        }
    }
    __syncthreads();
    if (tid < 128) {
        float s = sRed[tid] + sRed[128 + tid];
        float* dst = half ? g_aggB : g_aggA;
        dst[(size_t)(bb * 128 + p) * 128 + tid] = s;
    }
}

// ---------------------------------------------------------------------------
// node update + BN : 512 blocks x 4 rows; agg = aggA + aggB
// ---------------------------------------------------------------------------
__global__ __launch_bounds__(256) void node_kernel(
    const float* __restrict__ W1u, const float* __restrict__ b1u,
    const float* __restrict__ W2u, const float* __restrict__ b2u,
    const float* __restrict__ gamma_n, const float* __restrict__ beta_n,
    const float* __restrict__ mean_n,  const float* __restrict__ var_n,
    float* __restrict__ nodes_out)
{
    __shared__ float sA[4 * 128];
    __shared__ float sH2[4 * 256];
    int row0 = blockIdx.x * 4;
    int tid = threadIdx.x;
    for (int i = tid; i < 512; i += 256)
        sA[i] = g_aggA[(size_t)row0 * 128 + i] + g_aggB[(size_t)row0 * 128 + i];
    __syncthreads();
    {
        float a[4];
        #pragma unroll
        for (int r = 0; r < 4; r++) a[r] = 0.f;
        const float* W = W1u + (size_t)128 * 256 + tid;
        #pragma unroll 4
        for (int kb = 0; kb < 128; kb += 4) {
            float w0 = W[(size_t)(kb + 0) * 256];
            float w1 = W[(size_t)(kb + 1) * 256];
            float w2 = W[(size_t)(kb + 2) * 256];
            float w3 = W[(size_t)(kb + 3) * 256];
            #pragma unroll
            for (int r = 0; r < 4; r++) {
                float4 xv = *(const float4*)(sA + r * 128 + kb);
                a[r] += xv.x * w0 + xv.y * w1 + xv.z * w2 + xv.w * w3;
            }
        }
        float bb1 = b1u[tid];
        #pragma unroll
        for (int r = 0; r < 4; r++) {
            float v = a[r] + g_Pu[(size_t)(row0 + r) * 256 + tid] + bb1;
            sH2[r * 256 + tid] = fmaxf(v, 0.f);
        }
    }
    __syncthreads();
    {
        int col = tid & 127;
        int rh  = tid >> 7;   // 0 or 1
        float c2[2] = {0.f, 0.f};
        const float* W2 = W2u + col;
        #pragma unroll 4
        for (int kb = 0; kb < 256; kb += 4) {
            float w0 = W2[(size_t)(kb + 0) * 128];
            float w1 = W2[(size_t)(kb + 1) * 128];
            float w2 = W2[(size_t)(kb + 2) * 128];
            float w3 = W2[(size_t)(kb + 3) * 128];
            #pragma unroll
            for (int rr = 0; rr < 2; rr++) {
                float4 hv = *(const float4*)(sH2 + (rh * 2 + rr) * 256 + kb);
                c2[rr] += hv.x * w0 + hv.y * w1 + hv.z * w2 + hv.w * w3;
            }
        }
        float bb2 = b2u[col];
        float s = gamma_n[col] * rsqrtf(var_n[col] + EPSBN);
        float sh = beta_n[col] - mean_n[col] * s;
        #pragma unroll
        for (int rr = 0; rr < 2; rr++) {
            float v = fmaxf(c2[rr] + bb2, 0.f);
            nodes_out[(size_t)(row0 + rh * 2 + rr) * 128 + col] = v * s + sh;
        }
    }
}

// ---------------------------------------------------------------------------
extern "C" void kernel_launch(void* const* d_in, const int* in_sizes, int n_in,
                              void* d_out, int out_size)
{
    const float* nodes = (const float*)d_in[0];
    const float* edges = (const float*)d_in[1];
    const float* mask  = (const float*)d_in[2];
    const float* W1a = (const float*)d_in[3];
    const float* b1a = (const float*)d_in[4];
    const float* W2a = (const float*)d_in[5];
    const float* b2a = (const float*)d_in[6];
    const float* W1m = (const float*)d_in[7];
    const float* b1m = (const float*)d_in[8];
    const float* W2m = (const float*)d_in[9];
    const float* b2m = (const float*)d_in[10];
    const float* W1u = (const float*)d_in[11];
    const float* b1u = (const float*)d_in[12];
    const float* W2u = (const float*)d_in[13];
    const float* b2u = (const float*)d_in[14];
    const float* gamma_n = (const float*)d_in[15];
    const float* beta_n  = (const float*)d_in[16];
    const float* mean_n  = (const float*)d_in[17];
    const float* var_n   = (const float*)d_in[18];
    const float* gamma_e = (const float*)d_in[19];
    const float* beta_e  = (const float*)d_in[20];
    const float* mean_e  = (const float*)d_in[21];
    const float* var_e   = (const float*)d_in[22];

    float* out = (float*)d_out;
    float* nodes_out = out;
    float* edges_out = out + (size_t)16 * 128 * 128;

    cudaFuncSetAttribute(edge_kernel, cudaFuncAttributeMaxDynamicSharedMemorySize,
                         (int)SMEM_EDGE_BYTES);

    prep_kernel<<<648, 256>>>(nodes, W1a, W2a, W1m, W2m, W1u);

    dim3 gridB(256, 16);
    edge_kernel<<<gridB, 256, SMEM_EDGE_BYTES>>>(edges, mask,
                                                 b1a, b2a, b1m, b2m,
                                                 gamma_e, beta_e, mean_e, var_e,
                                                 edges_out);

    node_kernel<<<512, 256>>>(W1u, b1u, W2u, b2u,
                              gamma_n, beta_n, mean_n, var_n,
                              nodes_out);
}

// round 16
// speedup vs baseline: 1.1318x; 1.0279x over previous
#include <cuda_runtime.h>
#include <cuda_fp16.h>
#include <cstdint>
#include <math.h>

#define EPSBN 1e-3f

// ---------------- device scratch (no allocation allowed) ----------------
__device__ __align__(16) float  g_Pi_a[2048 * 256];
__device__ __align__(16) float  g_Pj_a[2048 * 256];
__device__ __align__(16) float  g_Pi_m[2048 * 256];
__device__ __align__(16) float  g_Pj_m[2048 * 256];
__device__ __align__(16) float  g_Pu [2048 * 256];
__device__ __align__(16) float  g_aggA[2048 * 128];   // partial agg, rows 0-63
__device__ __align__(16) float  g_aggB[2048 * 128];   // partial agg, rows 64-127
// slabs: g0/g1/g3/g4: [n=128][k=128]; g2/g5: [n=128][k=256]  (B[n][k]=W[k][n])
__device__ __align__(16) __half g_WT[131072];
__constant__ int c_OW[6] = {0, 16384, 32768, 65536, 81920, 98304};  // half offsets

// ---------------- PTX helpers (baseline sm_80+, safe for sm_103) --------
__device__ __forceinline__ uint32_t smem_u32(const void* p) {
    uint32_t a;
    asm("{ .reg .u64 t; cvta.to.shared.u64 t, %1; cvt.u32.u64 %0, t; }" : "=r"(a) : "l"(p));
    return a;
}
__device__ __forceinline__ void cp16(uint32_t s, const void* g) {
    asm volatile("cp.async.cg.shared.global [%0], [%1], 16;" :: "r"(s), "l"(g));
}
#define CP_COMMIT() asm volatile("cp.async.commit_group;" ::: "memory")
#define CP_WAIT0()  asm volatile("cp.async.wait_group 0;" ::: "memory")

__device__ __forceinline__ void ldsm4(uint32_t& r0, uint32_t& r1, uint32_t& r2, uint32_t& r3,
                                      uint32_t addr) {
    asm volatile("ldmatrix.sync.aligned.m8n8.x4.shared.b16 {%0,%1,%2,%3}, [%4];"
                 : "=r"(r0), "=r"(r1), "=r"(r2), "=r"(r3) : "r"(addr));
}
__device__ __forceinline__ void mma16816(float* c, const uint32_t* a, uint32_t b0, uint32_t b1) {
    asm volatile("mma.sync.aligned.m16n8k16.row.col.f32.f16.f16.f32 "
                 "{%0,%1,%2,%3},{%4,%5,%6,%7},{%8,%9},{%0,%1,%2,%3};"
                 : "+f"(c[0]), "+f"(c[1]), "+f"(c[2]), "+f"(c[3])
                 : "r"(a[0]), "r"(a[1]), "r"(a[2]), "r"(a[3]), "r"(b0), "r"(b1));
}

// ---------------- SMEM layout (bytes) ----------------
// sA: 64 x (128+8) f16 ; sH: 64 x (256+8) f16 ; sB: 128 n x (128+8) k f16
#define LDAE 136
#define LDH  264
#define OFF_A    0u         // 17408
#define OFF_H    17408u     // 33792
#define OFF_B    51200u     // 34816
#define OFF_BIAS 86016u     // 128 f32
#define OFF_MASK 86528u     // 64 f32
#define OFF_SCL  86784u     // 128 f32
#define OFF_SHF  87296u     // 128 f32
#define OFF_RED  87808u     // 2 x 128 f32
#define SMEM_EDGE_BYTES 88832u

// ---------------------------------------------------------------------------
// prep: blocks 0..639 -> Pi_a/Pj_a/Pi_m/Pj_m/Pu (16 rows each) ;
//       blocks 640..647 -> g_WT
// ---------------------------------------------------------------------------
__global__ __launch_bounds__(256) void prep_kernel(
    const float* __restrict__ nodes,
    const float* __restrict__ W1a, const float* __restrict__ W2a,
    const float* __restrict__ W1m, const float* __restrict__ W2m,
    const float* __restrict__ W1u)
{
    int blk = blockIdx.x, tid = threadIdx.x;
    if (blk < 640) {
        __shared__ float sX[2048];
        int m = blk >> 7, row0 = (blk & 127) * 16;
        for (int i = tid; i < 2048; i += 256) sX[i] = nodes[(size_t)row0 * 128 + i];
        __syncthreads();
        const float* W;
        float* O;
        switch (m) {
            case 0: W = W1a;             O = g_Pi_a; break;
            case 1: W = W1a + 128 * 256; O = g_Pj_a; break;
            case 2: W = W1m;             O = g_Pi_m; break;
            case 3: W = W1m + 128 * 256; O = g_Pj_m; break;
            default: W = W1u;            O = g_Pu;   break;
        }
        W += tid;
        O += (size_t)row0 * 256 + tid;
        float a[16];
        #pragma unroll
        for (int r = 0; r < 16; r++) a[r] = 0.f;
        #pragma unroll 4
        for (int kb = 0; kb < 128; kb += 4) {
            float w0 = W[(size_t)(kb + 0) * 256];
            float w1 = W[(size_t)(kb + 1) * 256];
            float w2 = W[(size_t)(kb + 2) * 256];
            float w3 = W[(size_t)(kb + 3) * 256];
            #pragma unroll
            for (int r = 0; r < 16; r++) {
                float4 xv = *(const float4*)(sX + r * 128 + kb);
                a[r] += xv.x * w0 + xv.y * w1 + xv.z * w2 + xv.w * w3;
            }
        }
        #pragma unroll
        for (int r = 0; r < 16; r++) O[(size_t)r * 256] = a[r];
        return;
    }
    int c = blk - 640;  // 0..7
    int slab, nbase;
    if      (c == 0) { slab = 0; nbase = 0; }
    else if (c == 1) { slab = 1; nbase = 0; }
    else if (c <= 3) { slab = 2; nbase = (c - 2) * 64; }
    else if (c == 4) { slab = 3; nbase = 0; }
    else if (c == 5) { slab = 4; nbase = 0; }
    else             { slab = 5; nbase = (c - 6) * 64; }
    int K = (slab == 2 || slab == 5) ? 256 : 128;
    int nrows = (slab == 2 || slab == 5) ? 64 : 128;
    __half* dst = g_WT + c_OW[slab] + (size_t)nbase * K;
    for (int e = tid; e < nrows * K; e += 256) {
        int n = nbase + e / K;
        int k = e % K;
        float v;
        if      (slab == 0) v = W1a[(size_t)(256 + k) * 256 + n];
        else if (slab == 1) v = W1a[(size_t)(256 + k) * 256 + 128 + n];
        else if (slab == 2) v = W2a[(size_t)k * 128 + n];
        else if (slab == 3) v = W1m[(size_t)(256 + k) * 256 + n];
        else if (slab == 4) v = W1m[(size_t)(256 + k) * 256 + 128 + n];
        else                v = W2m[(size_t)k * 128 + n];
        dst[e] = __float2half_rn(v);
    }
}

// ---------------------------------------------------------------------------
// edge kernel: M=64 tile, 8 K=128 chunk phases, single B buffer, 2 CTAs/SM
// K-loop software-pipelined in registers (ldsm kt+1 issued before mma kt)
// chunk -> (slab, khalf): 0:(0,0) 1:(1,0) 2:(2,0) 3:(2,1) 4:(3,0) 5:(4,0) 6:(5,0) 7:(5,1)
// ---------------------------------------------------------------------------
__device__ __forceinline__ void cp_chunk(uint32_t sbase, int i, int tid) {
    static const int chS[8] = {0, 1, 2, 2, 3, 4, 5, 5};
    static const int chH[8] = {0, 0, 0, 1, 0, 0, 0, 1};
    int s = chS[i], h = chH[i];
    int K = (s == 2 || s == 5) ? 256 : 128;
    const __half* src = g_WT + c_OW[s] + h * 128;
    #pragma unroll
    for (int j = 0; j < 8; j++) {
        int f = tid + j * 256;
        int n = f >> 4, sub = f & 15;
        cp16(sbase + OFF_B + (uint32_t)(n * (LDAE * 2) + sub * 16),
             src + (size_t)n * K + sub * 8);
    }
    CP_COMMIT();
}

// 32x32 warp tile, K=128, register-double-buffered fragment pipeline
template <int LDA_>
__device__ __forceinline__ void kloop(uint32_t aBase, uint32_t bBase,
                                      int m0, int n0, int aRow, int aK, int bRow, int bK,
                                      float (&acc)[2][4][4])
{
    uint32_t a0[2][4], a1[2][4], bf[2][8];
    // prologue: load fragments for kt = 0 into buffer 0
    ldsm4(a0[0][0], a0[0][1], a0[0][2], a0[0][3],
          aBase + (uint32_t)(((m0 + aRow) * LDA_ + aK) << 1));
    ldsm4(a1[0][0], a1[0][1], a1[0][2], a1[0][3],
          aBase + (uint32_t)(((m0 + 16 + aRow) * LDA_ + aK) << 1));
    #pragma unroll
    for (int pp = 0; pp < 2; pp++)
        ldsm4(bf[0][pp * 4], bf[0][pp * 4 + 1], bf[0][pp * 4 + 2], bf[0][pp * 4 + 3],
              bBase + (uint32_t)(((n0 + pp * 16 + bRow) * LDAE + bK) << 1));

    #pragma unroll
    for (int kt = 0; kt < 8; kt++) {
        int cur = kt & 1, nxt = cur ^ 1;
        if (kt < 7) {
            int kg = (kt + 1) * 16;
            ldsm4(a0[nxt][0], a0[nxt][1], a0[nxt][2], a0[nxt][3],
                  aBase + (uint32_t)(((m0 + aRow) * LDA_ + kg + aK) << 1));
            ldsm4(a1[nxt][0], a1[nxt][1], a1[nxt][2], a1[nxt][3],
                  aBase + (uint32_t)(((m0 + 16 + aRow) * LDA_ + kg + aK) << 1));
            #pragma unroll
            for (int pp = 0; pp < 2; pp++)
                ldsm4(bf[nxt][pp * 4], bf[nxt][pp * 4 + 1],
                      bf[nxt][pp * 4 + 2], bf[nxt][pp * 4 + 3],
                      bBase + (uint32_t)(((n0 + pp * 16 + bRow) * LDAE + kg + bK) << 1));
        }
        #pragma unroll
        for (int nt = 0; nt < 4; nt++) {
            uint32_t bb0 = bf[cur][(nt >> 1) * 4 + (nt & 1) * 2];
            uint32_t bb1 = bf[cur][(nt >> 1) * 4 + (nt & 1) * 2 + 1];
            mma16816(acc[0][nt], a0[cur], bb0, bb1);
            mma16816(acc[1][nt], a1[cur], bb0, bb1);
        }
    }
}

__global__ __launch_bounds__(256, 2) void edge_kernel(
    const float* __restrict__ edges, const float* __restrict__ mask,
    const float* __restrict__ b1a, const float* __restrict__ b2a,
    const float* __restrict__ b1m, const float* __restrict__ b2m,
    const float* __restrict__ gamma_e, const float* __restrict__ beta_e,
    const float* __restrict__ mean_e,  const float* __restrict__ var_e,
    float* __restrict__ edges_out)
{
    extern __shared__ char smc[];
    uint32_t sbase = smem_u32(smc);
    int p = blockIdx.x >> 1, half = blockIdx.x & 1, bb = blockIdx.y;
    int tid = threadIdx.x, lane = tid & 31, w = tid >> 5;
    int wm = w >> 2, wn = w & 3;          // 2 x 4 warp grid, 32x32 tiles
    int m0 = wm * 32, n0 = wn * 32;

    float* sBias = (float*)(smc + OFF_BIAS);
    float* sMask = (float*)(smc + OFF_MASK);
    float* sScl  = (float*)(smc + OFF_SCL);
    float* sShf  = (float*)(smc + OFF_SHF);
    float* sRed  = (float*)(smc + OFF_RED);

    int aRow = lane & 15;
    int aK   = (lane & 16) ? 8 : 0;
    int bRow = (lane & 7) + ((lane & 16) ? 8 : 0);
    int bK   = (lane & 8) ? 8 : 0;
    int tq = lane >> 2;
    int tc = (lane & 3) * 2;

    cp_chunk(sbase, 0, tid);   // prefetch chunk 0 (overlaps E-tile load)

    const size_t tb   = (size_t)(bb * 128 + p) * 256;
    const size_t pib  = (size_t)bb * 128 * 256;
    const int    row0 = half * 64;                 // global row base of this CTA

    // ---- load E tile (64 rows, fp16) + consts
    {
        const float4* Eg = (const float4*)(edges +
            (size_t)(bb * 16384 + p * 128 + row0) * 128);
        #pragma unroll 4
        for (int i = tid; i < 2048; i += 256) {
            int qq = i >> 5, k4 = (i & 31) << 2;
            float4 e = __ldg(Eg + i);
            __half2 e0 = __floats2half2_rn(e.x, e.y), e1 = __floats2half2_rn(e.z, e.w);
            *(uint2*)(smc + OFF_A + (size_t)((qq * LDAE + k4) << 1)) =
                make_uint2(*(uint32_t*)&e0, *(uint32_t*)&e1);
        }
        if (tid < 64)
            sMask[tid] = __ldg(mask + (size_t)bb * 16384 + p * 128 + row0 + tid);
        if (tid >= 128 && tid < 256) {
            int c = tid - 128;
            float s = __ldg(gamma_e + c) * rsqrtf(__ldg(var_e + c) + EPSBN);
            sScl[c] = s;
            sShf[c] = __ldg(beta_e + c) - __ldg(mean_e + c) * s;
        }
    }

    float acc[2][4][4];
    float2 pi1[2][4], pi2[2][4];

    static const int chS[8]       = {0, 1, 2, 2, 3, 4, 5, 5};
    static const int chNewSlab[8] = {1, 1, 1, 0, 1, 1, 1, 0};
    static const int chSlabEnd[8] = {1, 1, 0, 1, 1, 1, 0, 1};

    #pragma unroll 1
    for (int i = 0; i < 8; i++) {
        CP_WAIT0();
        __syncthreads();

        int s = chS[i];
        int h = (i == 3 || i == 7) ? 1 : 0;
        bool isH1 = (s == 0 || s == 1 || s == 3 || s == 4);
        int hb = (s == 1 || s == 4) ? 128 : 0;

        if (chNewSlab[i]) {
            if (tid < 128) {
                float bz;
                if      (s == 0) bz = __ldg(b1a + tid)       + g_Pj_a[tb + tid];
                else if (s == 1) bz = __ldg(b1a + 128 + tid) + g_Pj_a[tb + 128 + tid];
                else if (s == 2) bz = __ldg(b2a + tid);
                else if (s == 3) bz = __ldg(b1m + tid)       + g_Pj_m[tb + tid];
                else if (s == 4) bz = __ldg(b1m + 128 + tid) + g_Pj_m[tb + 128 + tid];
                else             bz = __ldg(b2m + tid);
                sBias[tid] = bz;
            }
            #pragma unroll
            for (int mt = 0; mt < 2; mt++)
                #pragma unroll
                for (int nt = 0; nt < 4; nt++)
                    #pragma unroll
                    for (int z = 0; z < 4; z++) acc[mt][nt][z] = 0.f;
            if (isH1) {
                const float* Pi = (s < 2 ? g_Pi_a : g_Pi_m) + pib + hb;
                #pragma unroll
                for (int mt = 0; mt < 2; mt++) {
                    int r1 = row0 + m0 + mt * 16 + tq, r2 = r1 + 8;
                    #pragma unroll
                    for (int nt = 0; nt < 4; nt++) {
                        int cc = n0 + nt * 8 + tc;
                        pi1[mt][nt] = __ldg((const float2*)(Pi + (size_t)r1 * 256 + cc));
                        pi2[mt][nt] = __ldg((const float2*)(Pi + (size_t)r2 * 256 + cc));
                    }
                }
            }
        }

        if (s == 2 || s == 5)
            kloop<LDH>(sbase + OFF_H + (uint32_t)(h * 256), sbase + OFF_B,
                       m0, n0, aRow, aK, bRow, bK, acc);
        else
            kloop<LDAE>(sbase + OFF_A, sbase + OFF_B,
                        m0, n0, aRow, aK, bRow, bK, acc);

        __syncthreads();                // all reads of sB done
        if (i < 7) cp_chunk(sbase, i + 1, tid);   // refill (overlaps epilogue)

        if (!chSlabEnd[i]) continue;

        // ---------------- epilogue ----------------
        if (isH1) {
            #pragma unroll
            for (int mt = 0; mt < 2; mt++) {
                int r1 = m0 + mt * 16 + tq, r2 = r1 + 8;
                #pragma unroll
                for (int nt = 0; nt < 4; nt++) {
                    int cc = n0 + nt * 8 + tc;
                    float bz0 = sBias[cc], bz1 = sBias[cc + 1];
                    float a0 = fmaxf(acc[mt][nt][0] + pi1[mt][nt].x + bz0, 0.f);
                    float a1 = fmaxf(acc[mt][nt][1] + pi1[mt][nt].y + bz1, 0.f);
                    float a2 = fmaxf(acc[mt][nt][2] + pi2[mt][nt].x + bz0, 0.f);
                    float a3 = fmaxf(acc[mt][nt][3] + pi2[mt][nt].y + bz1, 0.f);
                    __half2 h0 = __floats2half2_rn(a0, a1);
                    __half2 h1 = __floats2half2_rn(a2, a3);
                    *(uint32_t*)(smc + OFF_H + (size_t)((r1 * LDH + hb + cc) << 1)) = *(uint32_t*)&h0;
                    *(uint32_t*)(smc + OFF_H + (size_t)((r2 * LDH + hb + cc) << 1)) = *(uint32_t*)&h1;
                }
            }
        } else if (s == 2) {
            float* go = edges_out + ((size_t)bb * 16384 + (size_t)p * 128 + row0) * 128;
            #pragma unroll
            for (int mt = 0; mt < 2; mt++) {
                int r1 = m0 + mt * 16 + tq, r2 = r1 + 8;
                float mk1 = sMask[r1], mk2 = sMask[r2];
                #pragma unroll
                for (int nt = 0; nt < 4; nt++) {
                    int cc = n0 + nt * 8 + tc;
                    float bz0 = sBias[cc], bz1 = sBias[cc + 1];
                    float v0 = fmaxf(acc[mt][nt][0] + bz0, 0.f) * mk1;
                    float v1 = fmaxf(acc[mt][nt][1] + bz1, 0.f) * mk1;
                    float v2 = fmaxf(acc[mt][nt][2] + bz0, 0.f) * mk2;
                    float v3 = fmaxf(acc[mt][nt][3] + bz1, 0.f) * mk2;
                    float s0 = sScl[cc], s1 = sScl[cc + 1];
                    float f0 = sShf[cc], f1 = sShf[cc + 1];
                    *(float2*)(go + (size_t)r1 * 128 + cc) = make_float2(v0 * s0 + f0, v1 * s1 + f1);
                    *(float2*)(go + (size_t)r2 * 128 + cc) = make_float2(v2 * s0 + f0, v3 * s1 + f1);
                    __half2 h0 = __floats2half2_rn(v0, v1);
                    __half2 h1 = __floats2half2_rn(v2, v3);
                    *(uint32_t*)(smc + OFF_A + (size_t)((r1 * LDAE + cc) << 1)) = *(uint32_t*)&h0;
                    *(uint32_t*)(smc + OFF_A + (size_t)((r2 * LDAE + cc) << 1)) = *(uint32_t*)&h1;
                }
            }
        } else {  // s == 5 : masked column sums over this CTA's 64 rows
            #pragma unroll
            for (int nt = 0; nt < 4; nt++) {
                int cc = n0 + nt * 8 + tc;
                float bz0 = sBias[cc], bz1 = sBias[cc + 1];
                float s0 = 0.f, s1 = 0.f;
                #pragma unroll
                for (int mt = 0; mt < 2; mt++) {
                    int r1 = m0 + mt * 16 + tq, r2 = r1 + 8;
                    float mk1 = sMask[r1], mk2 = sMask[r2];
                    s0 += fmaxf(acc[mt][nt][0] + bz0, 0.f) * mk1
                        + fmaxf(acc[mt][nt][2] + bz0, 0.f) * mk2;
                    s1 += fmaxf(acc[mt][nt][1] + bz1, 0.f) * mk1
                        + fmaxf(acc[mt][nt][3] + bz1, 0.f) * mk2;
                }
                #pragma unroll
                for (int d = 4; d < 32; d <<= 1) {
                    s0 += __shfl_xor_sync(0xffffffffu, s0, d);
                    s1 += __shfl_xor_sync(0xffffffffu, s1, d);
                }
                if (lane < 4) {
                    sRed[wm * 128 + cc]     = s0;
                    sRed[wm * 128 + cc + 1] = s1;
                }
            }
        }
    }
    __syncthreads();
    if (tid < 128) {
        float s = sRed[tid] + sRed[128 + tid];
        float* dst = half ? g_aggB : g_aggA;
        dst[(size_t)(bb * 128 + p) * 128 + tid] = s;
    }
}

// ---------------------------------------------------------------------------
// node update + BN : 512 blocks x 4 rows; agg = aggA + aggB
// ---------------------------------------------------------------------------
__global__ __launch_bounds__(256) void node_kernel(
    const float* __restrict__ W1u, const float* __restrict__ b1u,
    const float* __restrict__ W2u, const float* __restrict__ b2u,
    const float* __restrict__ gamma_n, const float* __restrict__ beta_n,
    const float* __restrict__ mean_n,  const float* __restrict__ var_n,
    float* __restrict__ nodes_out)
{
    __shared__ float sA[4 * 128];
    __shared__ float sH2[4 * 256];
    int row0 = blockIdx.x * 4;
    int tid = threadIdx.x;
    for (int i = tid; i < 512; i += 256)
        sA[i] = g_aggA[(size_t)row0 * 128 + i] + g_aggB[(size_t)row0 * 128 + i];
    __syncthreads();
    {
        float a[4];
        #pragma unroll
        for (int r = 0; r < 4; r++) a[r] = 0.f;
        const float* W = W1u + (size_t)128 * 256 + tid;
        #pragma unroll 4
        for (int kb = 0; kb < 128; kb += 4) {
            float w0 = W[(size_t)(kb + 0) * 256];
            float w1 = W[(size_t)(kb + 1) * 256];
            float w2 = W[(size_t)(kb + 2) * 256];
            float w3 = W[(size_t)(kb + 3) * 256];
            #pragma unroll
            for (int r = 0; r < 4; r++) {
                float4 xv = *(const float4*)(sA + r * 128 + kb);
                a[r] += xv.x * w0 + xv.y * w1 + xv.z * w2 + xv.w * w3;
            }
        }
        float bb1 = b1u[tid];
        #pragma unroll
        for (int r = 0; r < 4; r++) {
            float v = a[r] + g_Pu[(size_t)(row0 + r) * 256 + tid] + bb1;
            sH2[r * 256 + tid] = fmaxf(v, 0.f);
        }
    }
    __syncthreads();
    {
        int col = tid & 127;
        int rh  = tid >> 7;   // 0 or 1
        float c2[2] = {0.f, 0.f};
        const float* W2 = W2u + col;
        #pragma unroll 4
        for (int kb = 0; kb < 256; kb += 4) {
            float w0 = W2[(size_t)(kb + 0) * 128];
            float w1 = W2[(size_t)(kb + 1) * 128];
            float w2 = W2[(size_t)(kb + 2) * 128];
            float w3 = W2[(size_t)(kb + 3) * 128];
            #pragma unroll
            for (int rr = 0; rr < 2; rr++) {
                float4 hv = *(const float4*)(sH2 + (rh * 2 + rr) * 256 + kb);
                c2[rr] += hv.x * w0 + hv.y * w1 + hv.z * w2 + hv.w * w3;
            }
        }
        float bb2 = b2u[col];
        float s = gamma_n[col] * rsqrtf(var_n[col] + EPSBN);
        float sh = beta_n[col] - mean_n[col] * s;
        #pragma unroll
        for (int rr = 0; rr < 2; rr++) {
            float v = fmaxf(c2[rr] + bb2, 0.f);
            nodes_out[(size_t)(row0 + rh * 2 + rr) * 128 + col] = v * s + sh;
        }
    }
}

// ---------------------------------------------------------------------------
extern "C" void kernel_launch(void* const* d_in, const int* in_sizes, int n_in,
                              void* d_out, int out_size)
{
    const float* nodes = (const float*)d_in[0];
    const float* edges = (const float*)d_in[1];
    const float* mask  = (const float*)d_in[2];
    const float* W1a = (const float*)d_in[3];
    const float* b1a = (const float*)d_in[4];
    const float* W2a = (const float*)d_in[5];
    const float* b2a = (const float*)d_in[6];
    const float* W1m = (const float*)d_in[7];
    const float* b1m = (const float*)d_in[8];
    const float* W2m = (const float*)d_in[9];
    const float* b2m = (const float*)d_in[10];
    const float* W1u = (const float*)d_in[11];
    const float* b1u = (const float*)d_in[12];
    const float* W2u = (const float*)d_in[13];
    const float* b2u = (const float*)d_in[14];
    const float* gamma_n = (const float*)d_in[15];
    const float* beta_n  = (const float*)d_in[16];
    const float* mean_n  = (const float*)d_in[17];
    const float* var_n   = (const float*)d_in[18];
    const float* gamma_e = (const float*)d_in[19];
    const float* beta_e  = (const float*)d_in[20];
    const float* mean_e  = (const float*)d_in[21];
    const float* var_e   = (const float*)d_in[22];

    float* out = (float*)d_out;
    float* nodes_out = out;
    float* edges_out = out + (size_t)16 * 128 * 128;

    cudaFuncSetAttribute(edge_kernel, cudaFuncAttributeMaxDynamicSharedMemorySize,
                         (int)SMEM_EDGE_BYTES);

    prep_kernel<<<648, 256>>>(nodes, W1a, W2a, W1m, W2m, W1u);

    dim3 gridB(256, 16);
    edge_kernel<<<gridB, 256, SMEM_EDGE_BYTES>>>(edges, mask,
                                                 b1a, b2a, b1m, b2m,
                                                 gamma_e, beta_e, mean_e, var_e,
                                                 edges_out);

    node_kernel<<<512, 256>>>(W1u, b1u, W2u, b2u,
                              gamma_n, beta_n, mean_n, var_n,
                              nodes_out);
}

// round 17
// speedup vs baseline: 1.1910x; 1.0522x over previous
#include <cuda_runtime.h>
#include <cuda_fp16.h>
#include <cstdint>
#include <math.h>

#define EPSBN 1e-3f

// ---------------- device scratch (no allocation allowed) ----------------
__device__ __align__(16) float  g_Pi_a[2048 * 256];
__device__ __align__(16) float  g_Pj_a[2048 * 256];
__device__ __align__(16) float  g_Pi_m[2048 * 256];
__device__ __align__(16) float  g_Pj_m[2048 * 256];
__device__ __align__(16) float  g_Pu [2048 * 256];
__device__ __align__(16) float  g_aggA[2048 * 128];   // partial agg, rows 0-63
__device__ __align__(16) float  g_aggB[2048 * 128];   // partial agg, rows 64-127
// slabs: g0/g1/g3/g4: [n=128][k=128]; g2/g5: [n=128][k=256]  (B[n][k]=W[k][n])
__device__ __align__(16) __half g_WT[131072];
__constant__ int c_OW[6] = {0, 16384, 32768, 65536, 81920, 98304};  // half offsets

// ---------------- PTX helpers (baseline sm_80+, safe for sm_103) --------
__device__ __forceinline__ uint32_t smem_u32(const void* p) {
    uint32_t a;
    asm("{ .reg .u64 t; cvta.to.shared.u64 t, %1; cvt.u32.u64 %0, t; }" : "=r"(a) : "l"(p));
    return a;
}
__device__ __forceinline__ void cp16(uint32_t s, const void* g) {
    asm volatile("cp.async.cg.shared.global [%0], [%1], 16;" :: "r"(s), "l"(g));
}
#define CP_COMMIT() asm volatile("cp.async.commit_group;" ::: "memory")
#define CP_WAIT0()  asm volatile("cp.async.wait_group 0;" ::: "memory")

__device__ __forceinline__ void ldsm4(uint32_t& r0, uint32_t& r1, uint32_t& r2, uint32_t& r3,
                                      uint32_t addr) {
    asm volatile("ldmatrix.sync.aligned.m8n8.x4.shared.b16 {%0,%1,%2,%3}, [%4];"
                 : "=r"(r0), "=r"(r1), "=r"(r2), "=r"(r3) : "r"(addr));
}
__device__ __forceinline__ void mma16816(float* c, const uint32_t* a, uint32_t b0, uint32_t b1) {
    asm volatile("mma.sync.aligned.m16n8k16.row.col.f32.f16.f16.f32 "
                 "{%0,%1,%2,%3},{%4,%5,%6,%7},{%8,%9},{%0,%1,%2,%3};"
                 : "+f"(c[0]), "+f"(c[1]), "+f"(c[2]), "+f"(c[3])
                 : "r"(a[0]), "r"(a[1]), "r"(a[2]), "r"(a[3]), "r"(b0), "r"(b1));
}

// ---------------- SMEM layout (bytes) ----------------
// sA: 64 x (128+8) f16 ; sH: 64 x (256+8) f16 ; sB: 128 n x (128+8) k f16
#define LDAE 136
#define LDH  264
#define OFF_A    0u         // 17408
#define OFF_H    17408u     // 33792
#define OFF_B    51200u     // 34816
#define OFF_BIAS 86016u     // 128 f32
#define OFF_MASK 86528u     // 64 f32
#define OFF_SCL  86784u     // 128 f32
#define OFF_SHF  87296u     // 128 f32
#define OFF_RED  87808u     // 2 x 128 f32
#define SMEM_EDGE_BYTES 88832u

// ---------------------------------------------------------------------------
// prep: blocks 0..639 -> Pi_a/Pj_a/Pi_m/Pj_m/Pu (16 rows each) ;
//       blocks 640..647 -> g_WT
// ---------------------------------------------------------------------------
__global__ __launch_bounds__(256) void prep_kernel(
    const float* __restrict__ nodes,
    const float* __restrict__ W1a, const float* __restrict__ W2a,
    const float* __restrict__ W1m, const float* __restrict__ W2m,
    const float* __restrict__ W1u)
{
    int blk = blockIdx.x, tid = threadIdx.x;
    if (blk < 640) {
        __shared__ float sX[2048];
        int m = blk >> 7, row0 = (blk & 127) * 16;
        for (int i = tid; i < 2048; i += 256) sX[i] = nodes[(size_t)row0 * 128 + i];
        __syncthreads();
        const float* W;
        float* O;
        switch (m) {
            case 0: W = W1a;             O = g_Pi_a; break;
            case 1: W = W1a + 128 * 256; O = g_Pj_a; break;
            case 2: W = W1m;             O = g_Pi_m; break;
            case 3: W = W1m + 128 * 256; O = g_Pj_m; break;
            default: W = W1u;            O = g_Pu;   break;
        }
        W += tid;
        O += (size_t)row0 * 256 + tid;
        float a[16];
        #pragma unroll
        for (int r = 0; r < 16; r++) a[r] = 0.f;
        #pragma unroll 4
        for (int kb = 0; kb < 128; kb += 4) {
            float w0 = W[(size_t)(kb + 0) * 256];
            float w1 = W[(size_t)(kb + 1) * 256];
            float w2 = W[(size_t)(kb + 2) * 256];
            float w3 = W[(size_t)(kb + 3) * 256];
            #pragma unroll
            for (int r = 0; r < 16; r++) {
                float4 xv = *(const float4*)(sX + r * 128 + kb);
                a[r] += xv.x * w0 + xv.y * w1 + xv.z * w2 + xv.w * w3;
            }
        }
        #pragma unroll
        for (int r = 0; r < 16; r++) O[(size_t)r * 256] = a[r];
        return;
    }
    int c = blk - 640;  // 0..7
    int slab, nbase;
    if      (c == 0) { slab = 0; nbase = 0; }
    else if (c == 1) { slab = 1; nbase = 0; }
    else if (c <= 3) { slab = 2; nbase = (c - 2) * 64; }
    else if (c == 4) { slab = 3; nbase = 0; }
    else if (c == 5) { slab = 4; nbase = 0; }
    else             { slab = 5; nbase = (c - 6) * 64; }
    int K = (slab == 2 || slab == 5) ? 256 : 128;
    int nrows = (slab == 2 || slab == 5) ? 64 : 128;
    __half* dst = g_WT + c_OW[slab] + (size_t)nbase * K;
    for (int e = tid; e < nrows * K; e += 256) {
        int n = nbase + e / K;
        int k = e % K;
        float v;
        if      (slab == 0) v = W1a[(size_t)(256 + k) * 256 + n];
        else if (slab == 1) v = W1a[(size_t)(256 + k) * 256 + 128 + n];
        else if (slab == 2) v = W2a[(size_t)k * 128 + n];
        else if (slab == 3) v = W1m[(size_t)(256 + k) * 256 + n];
        else if (slab == 4) v = W1m[(size_t)(256 + k) * 256 + 128 + n];
        else                v = W2m[(size_t)k * 128 + n];
        dst[e] = __float2half_rn(v);
    }
}

// ---------------------------------------------------------------------------
// edge kernel: M=64 tile, 8 K=128 chunk phases (FULLY UNROLLED), single B
// buffer, 2 CTAs/SM, register-pipelined K-loop (R15 winner + unroll)
// chunk -> (slab, khalf): 0:(0,0) 1:(1,0) 2:(2,0) 3:(2,1) 4:(3,0) 5:(4,0) 6:(5,0) 7:(5,1)
// ---------------------------------------------------------------------------
__device__ __forceinline__ void cp_chunk(uint32_t sbase, int i, int tid) {
    static const int chS[8] = {0, 1, 2, 2, 3, 4, 5, 5};
    static const int chH[8] = {0, 0, 0, 1, 0, 0, 0, 1};
    int s = chS[i], h = chH[i];
    int K = (s == 2 || s == 5) ? 256 : 128;
    const __half* src = g_WT + c_OW[s] + h * 128;
    #pragma unroll
    for (int j = 0; j < 8; j++) {
        int f = tid + j * 256;
        int n = f >> 4, sub = f & 15;
        cp16(sbase + OFF_B + (uint32_t)(n * (LDAE * 2) + sub * 16),
             src + (size_t)n * K + sub * 8);
    }
    CP_COMMIT();
}

// 32x32 warp tile, K=128, register-double-buffered fragment pipeline
template <int LDA_>
__device__ __forceinline__ void kloop(uint32_t aBase, uint32_t bBase,
                                      int m0, int n0, int aRow, int aK, int bRow, int bK,
                                      float (&acc)[2][4][4])
{
    uint32_t a0[2][4], a1[2][4], bf[2][8];
    ldsm4(a0[0][0], a0[0][1], a0[0][2], a0[0][3],
          aBase + (uint32_t)(((m0 + aRow) * LDA_ + aK) << 1));
    ldsm4(a1[0][0], a1[0][1], a1[0][2], a1[0][3],
          aBase + (uint32_t)(((m0 + 16 + aRow) * LDA_ + aK) << 1));
    #pragma unroll
    for (int pp = 0; pp < 2; pp++)
        ldsm4(bf[0][pp * 4], bf[0][pp * 4 + 1], bf[0][pp * 4 + 2], bf[0][pp * 4 + 3],
              bBase + (uint32_t)(((n0 + pp * 16 + bRow) * LDAE + bK) << 1));

    #pragma unroll
    for (int kt = 0; kt < 8; kt++) {
        int cur = kt & 1, nxt = cur ^ 1;
        if (kt < 7) {
            int kg = (kt + 1) * 16;
            ldsm4(a0[nxt][0], a0[nxt][1], a0[nxt][2], a0[nxt][3],
                  aBase + (uint32_t)(((m0 + aRow) * LDA_ + kg + aK) << 1));
            ldsm4(a1[nxt][0], a1[nxt][1], a1[nxt][2], a1[nxt][3],
                  aBase + (uint32_t)(((m0 + 16 + aRow) * LDA_ + kg + aK) << 1));
            #pragma unroll
            for (int pp = 0; pp < 2; pp++)
                ldsm4(bf[nxt][pp * 4], bf[nxt][pp * 4 + 1],
                      bf[nxt][pp * 4 + 2], bf[nxt][pp * 4 + 3],
                      bBase + (uint32_t)(((n0 + pp * 16 + bRow) * LDAE + kg + bK) << 1));
        }
        #pragma unroll
        for (int nt = 0; nt < 4; nt++) {
            uint32_t bb0 = bf[cur][(nt >> 1) * 4 + (nt & 1) * 2];
            uint32_t bb1 = bf[cur][(nt >> 1) * 4 + (nt & 1) * 2 + 1];
            mma16816(acc[0][nt], a0[cur], bb0, bb1);
            mma16816(acc[1][nt], a1[cur], bb0, bb1);
        }
    }
}

__global__ __launch_bounds__(256, 2) void edge_kernel(
    const float* __restrict__ edges, const float* __restrict__ mask,
    const float* __restrict__ b1a, const float* __restrict__ b2a,
    const float* __restrict__ b1m, const float* __restrict__ b2m,
    const float* __restrict__ gamma_e, const float* __restrict__ beta_e,
    const float* __restrict__ mean_e,  const float* __restrict__ var_e,
    float* __restrict__ edges_out)
{
    extern __shared__ char smc[];
    uint32_t sbase = smem_u32(smc);
    int p = blockIdx.x >> 1, half = blockIdx.x & 1, bb = blockIdx.y;
    int tid = threadIdx.x, lane = tid & 31, w = tid >> 5;
    int wm = w >> 2, wn = w & 3;          // 2 x 4 warp grid, 32x32 tiles
    int m0 = wm * 32, n0 = wn * 32;

    float* sBias = (float*)(smc + OFF_BIAS);
    float* sMask = (float*)(smc + OFF_MASK);
    float* sScl  = (float*)(smc + OFF_SCL);
    float* sShf  = (float*)(smc + OFF_SHF);
    float* sRed  = (float*)(smc + OFF_RED);

    int aRow = lane & 15;
    int aK   = (lane & 16) ? 8 : 0;
    int bRow = (lane & 7) + ((lane & 16) ? 8 : 0);
    int bK   = (lane & 8) ? 8 : 0;
    int tq = lane >> 2;
    int tc = (lane & 3) * 2;

    cp_chunk(sbase, 0, tid);   // prefetch chunk 0 (overlaps E-tile load)

    const size_t tb   = (size_t)(bb * 128 + p) * 256;
    const size_t pib  = (size_t)bb * 128 * 256;
    const int    row0 = half * 64;                 // global row base of this CTA

    // ---- load E tile (64 rows, fp16) + consts
    {
        const float4* Eg = (const float4*)(edges +
            (size_t)(bb * 16384 + p * 128 + row0) * 128);
        #pragma unroll 4
        for (int i = tid; i < 2048; i += 256) {
            int qq = i >> 5, k4 = (i & 31) << 2;
            float4 e = __ldg(Eg + i);
            __half2 e0 = __floats2half2_rn(e.x, e.y), e1 = __floats2half2_rn(e.z, e.w);
            *(uint2*)(smc + OFF_A + (size_t)((qq * LDAE + k4) << 1)) =
                make_uint2(*(uint32_t*)&e0, *(uint32_t*)&e1);
        }
        if (tid < 64)
            sMask[tid] = __ldg(mask + (size_t)bb * 16384 + p * 128 + row0 + tid);
        if (tid >= 128 && tid < 256) {
            int c = tid - 128;
            float s = __ldg(gamma_e + c) * rsqrtf(__ldg(var_e + c) + EPSBN);
            sScl[c] = s;
            sShf[c] = __ldg(beta_e + c) - __ldg(mean_e + c) * s;
        }
    }

    float acc[2][4][4];
    float2 pi1[2][4], pi2[2][4];

    #pragma unroll
    for (int i = 0; i < 8; i++) {
        // compile-time phase constants (loop is fully unrolled)
        const int sArr[8]       = {0, 1, 2, 2, 3, 4, 5, 5};
        const int newSlabArr[8] = {1, 1, 1, 0, 1, 1, 1, 0};
        const int slabEndArr[8] = {1, 1, 0, 1, 1, 1, 0, 1};
        const int s = sArr[i];
        const int h = (i == 3 || i == 7) ? 1 : 0;
        const bool isH1 = (s == 0 || s == 1 || s == 3 || s == 4);
        const int hb = (s == 1 || s == 4) ? 128 : 0;

        CP_WAIT0();
        __syncthreads();

        if (newSlabArr[i]) {
            if (tid < 128) {
                float bz;
                if      (s == 0) bz = __ldg(b1a + tid)       + g_Pj_a[tb + tid];
                else if (s == 1) bz = __ldg(b1a + 128 + tid) + g_Pj_a[tb + 128 + tid];
                else if (s == 2) bz = __ldg(b2a + tid);
                else if (s == 3) bz = __ldg(b1m + tid)       + g_Pj_m[tb + tid];
                else if (s == 4) bz = __ldg(b1m + 128 + tid) + g_Pj_m[tb + 128 + tid];
                else             bz = __ldg(b2m + tid);
                sBias[tid] = bz;
            }
            #pragma unroll
            for (int mt = 0; mt < 2; mt++)
                #pragma unroll
                for (int nt = 0; nt < 4; nt++)
                    #pragma unroll
                    for (int z = 0; z < 4; z++) acc[mt][nt][z] = 0.f;
            if (isH1) {
                const float* Pi = (s < 2 ? g_Pi_a : g_Pi_m) + pib + hb;
                #pragma unroll
                for (int mt = 0; mt < 2; mt++) {
                    int r1 = row0 + m0 + mt * 16 + tq, r2 = r1 + 8;
                    #pragma unroll
                    for (int nt = 0; nt < 4; nt++) {
                        int cc = n0 + nt * 8 + tc;
                        pi1[mt][nt] = __ldg((const float2*)(Pi + (size_t)r1 * 256 + cc));
                        pi2[mt][nt] = __ldg((const float2*)(Pi + (size_t)r2 * 256 + cc));
                    }
                }
            }
        }

        if (s == 2 || s == 5)
            kloop<LDH>(sbase + OFF_H + (uint32_t)(h * 256), sbase + OFF_B,
                       m0, n0, aRow, aK, bRow, bK, acc);
        else
            kloop<LDAE>(sbase + OFF_A, sbase + OFF_B,
                        m0, n0, aRow, aK, bRow, bK, acc);

        __syncthreads();                // all reads of sB done
        if (i < 7) cp_chunk(sbase, i + 1, tid);   // refill (overlaps epilogue)

        if (slabEndArr[i]) {
            // ---------------- epilogue ----------------
            if (isH1) {
                #pragma unroll
                for (int mt = 0; mt < 2; mt++) {
                    int r1 = m0 + mt * 16 + tq, r2 = r1 + 8;
                    #pragma unroll
                    for (int nt = 0; nt < 4; nt++) {
                        int cc = n0 + nt * 8 + tc;
                        float bz0 = sBias[cc], bz1 = sBias[cc + 1];
                        float a0 = fmaxf(acc[mt][nt][0] + pi1[mt][nt].x + bz0, 0.f);
                        float a1 = fmaxf(acc[mt][nt][1] + pi1[mt][nt].y + bz1, 0.f);
                        float a2 = fmaxf(acc[mt][nt][2] + pi2[mt][nt].x + bz0, 0.f);
                        float a3 = fmaxf(acc[mt][nt][3] + pi2[mt][nt].y + bz1, 0.f);
                        __half2 h0 = __floats2half2_rn(a0, a1);
                        __half2 h1 = __floats2half2_rn(a2, a3);
                        *(uint32_t*)(smc + OFF_H + (size_t)((r1 * LDH + hb + cc) << 1)) = *(uint32_t*)&h0;
                        *(uint32_t*)(smc + OFF_H + (size_t)((r2 * LDH + hb + cc) << 1)) = *(uint32_t*)&h1;
                    }
                }
            } else if (s == 2) {
                float* go = edges_out + ((size_t)bb * 16384 + (size_t)p * 128 + row0) * 128;
                #pragma unroll
                for (int mt = 0; mt < 2; mt++) {
                    int r1 = m0 + mt * 16 + tq, r2 = r1 + 8;
                    float mk1 = sMask[r1], mk2 = sMask[r2];
                    #pragma unroll
                    for (int nt = 0; nt < 4; nt++) {
                        int cc = n0 + nt * 8 + tc;
                        float bz0 = sBias[cc], bz1 = sBias[cc + 1];
                        float v0 = fmaxf(acc[mt][nt][0] + bz0, 0.f) * mk1;
                        float v1 = fmaxf(acc[mt][nt][1] + bz1, 0.f) * mk1;
                        float v2 = fmaxf(acc[mt][nt][2] + bz0, 0.f) * mk2;
                        float v3 = fmaxf(acc[mt][nt][3] + bz1, 0.f) * mk2;
                        float s0 = sScl[cc], s1 = sScl[cc + 1];
                        float f0 = sShf[cc], f1 = sShf[cc + 1];
                        *(float2*)(go + (size_t)r1 * 128 + cc) = make_float2(v0 * s0 + f0, v1 * s1 + f1);
                        *(float2*)(go + (size_t)r2 * 128 + cc) = make_float2(v2 * s0 + f0, v3 * s1 + f1);
                        __half2 h0 = __floats2half2_rn(v0, v1);
                        __half2 h1 = __floats2half2_rn(v2, v3);
                        *(uint32_t*)(smc + OFF_A + (size_t)((r1 * LDAE + cc) << 1)) = *(uint32_t*)&h0;
                        *(uint32_t*)(smc + OFF_A + (size_t)((r2 * LDAE + cc) << 1)) = *(uint32_t*)&h1;
                    }
                }
            } else {  // s == 5 : masked column sums over this CTA's 64 rows
                #pragma unroll
                for (int nt = 0; nt < 4; nt++) {
                    int cc = n0 + nt * 8 + tc;
                    float bz0 = sBias[cc], bz1 = sBias[cc + 1];
                    float s0 = 0.f, s1 = 0.f;
                    #pragma unroll
                    for (int mt = 0; mt < 2; mt++) {
                        int r1 = m0 + mt * 16 + tq, r2 = r1 + 8;
                        float mk1 = sMask[r1], mk2 = sMask[r2];
                        s0 += fmaxf(acc[mt][nt][0] + bz0, 0.f) * mk1
                            + fmaxf(acc[mt][nt][2] + bz0, 0.f) * mk2;
                        s1 += fmaxf(acc[mt][nt][1] + bz1, 0.f) * mk1
                            + fmaxf(acc[mt][nt][3] + bz1, 0.f) * mk2;
                    }
                    #pragma unroll
                    for (int d = 4; d < 32; d <<= 1) {
                        s0 += __shfl_xor_sync(0xffffffffu, s0, d);
                        s1 += __shfl_xor_sync(0xffffffffu, s1, d);
                    }
                    if (lane < 4) {
                        sRed[wm * 128 + cc]     = s0;
                        sRed[wm * 128 + cc + 1] = s1;
                    }
                }
            }
        }
    }
    __syncthreads();
    if (tid < 128) {
        float s = sRed[tid] + sRed[128 + tid];
        float* dst = half ? g_aggB : g_aggA;
        dst[(size_t)(bb * 128 + p) * 128 + tid] = s;
    }
}

// ---------------------------------------------------------------------------
// node update + BN : 512 blocks x 4 rows; agg = aggA + aggB
// ---------------------------------------------------------------------------
__global__ __launch_bounds__(256) void node_kernel(
    const float* __restrict__ W1u, const float* __restrict__ b1u,
    const float* __restrict__ W2u, const float* __restrict__ b2u,
    const float* __restrict__ gamma_n, const float* __restrict__ beta_n,
    const float* __restrict__ mean_n,  const float* __restrict__ var_n,
    float* __restrict__ nodes_out)
{
    __shared__ float sA[4 * 128];
    __shared__ float sH2[4 * 256];
    int row0 = blockIdx.x * 4;
    int tid = threadIdx.x;
    for (int i = tid; i < 512; i += 256)
        sA[i] = g_aggA[(size_t)row0 * 128 + i] + g_aggB[(size_t)row0 * 128 + i];
    __syncthreads();
    {
        float a[4];
        #pragma unroll
        for (int r = 0; r < 4; r++) a[r] = 0.f;
        const float* W = W1u + (size_t)128 * 256 + tid;
        #pragma unroll 4
        for (int kb = 0; kb < 128; kb += 4) {
            float w0 = W[(size_t)(kb + 0) * 256];
            float w1 = W[(size_t)(kb + 1) * 256];
            float w2 = W[(size_t)(kb + 2) * 256];
            float w3 = W[(size_t)(kb + 3) * 256];
            #pragma unroll
            for (int r = 0; r < 4; r++) {
                float4 xv = *(const float4*)(sA + r * 128 + kb);
                a[r] += xv.x * w0 + xv.y * w1 + xv.z * w2 + xv.w * w3;
            }
        }
        float bb1 = b1u[tid];
        #pragma unroll
        for (int r = 0; r < 4; r++) {
            float v = a[r] + g_Pu[(size_t)(row0 + r) * 256 + tid] + bb1;
            sH2[r * 256 + tid] = fmaxf(v, 0.f);
        }
    }
    __syncthreads();
    {
        int col = tid & 127;
        int rh  = tid >> 7;   // 0 or 1
        float c2[2] = {0.f, 0.f};
        const float* W2 = W2u + col;
        #pragma unroll 4
        for (int kb = 0; kb < 256; kb += 4) {
            float w0 = W2[(size_t)(kb + 0) * 128];
            float w1 = W2[(size_t)(kb + 1) * 128];
            float w2 = W2[(size_t)(kb + 2) * 128];
            float w3 = W2[(size_t)(kb + 3) * 128];
            #pragma unroll
            for (int rr = 0; rr < 2; rr++) {
                float4 hv = *(const float4*)(sH2 + (rh * 2 + rr) * 256 + kb);
                c2[rr] += hv.x * w0 + hv.y * w1 + hv.z * w2 + hv.w * w3;
            }
        }
        float bb2 = b2u[col];
        float s = gamma_n[col] * rsqrtf(var_n[col] + EPSBN);
        float sh = beta_n[col] - mean_n[col] * s;
        #pragma unroll
        for (int rr = 0; rr < 2; rr++) {
            float v = fmaxf(c2[rr] + bb2, 0.f);
            nodes_out[(size_t)(row0 + rh * 2 + rr) * 128 + col] = v * s + sh;
        }
    }
}

// ---------------------------------------------------------------------------
extern "C" void kernel_launch(void* const* d_in, const int* in_sizes, int n_in,
                              void* d_out, int out_size)
{
    const float* nodes = (const float*)d_in[0];
    const float* edges = (const float*)d_in[1];
    const float* mask  = (const float*)d_in[2];
    const float* W1a = (const float*)d_in[3];
    const float* b1a = (const float*)d_in[4];
    const float* W2a = (const float*)d_in[5];
    const float* b2a = (const float*)d_in[6];
    const float* W1m = (const float*)d_in[7];
    const float* b1m = (const float*)d_in[8];
    const float* W2m = (const float*)d_in[9];
    const float* b2m = (const float*)d_in[10];
    const float* W1u = (const float*)d_in[11];
    const float* b1u = (const float*)d_in[12];
    const float* W2u = (const float*)d_in[13];
    const float* b2u = (const float*)d_in[14];
    const float* gamma_n = (const float*)d_in[15];
    const float* beta_n  = (const float*)d_in[16];
    const float* mean_n  = (const float*)d_in[17];
    const float* var_n   = (const float*)d_in[18];
    const float* gamma_e = (const float*)d_in[19];
    const float* beta_e  = (const float*)d_in[20];
    const float* mean_e  = (const float*)d_in[21];
    const float* var_e   = (const float*)d_in[22];

    float* out = (float*)d_out;
    float* nodes_out = out;
    float* edges_out = out + (size_t)16 * 128 * 128;

    cudaFuncSetAttribute(edge_kernel, cudaFuncAttributeMaxDynamicSharedMemorySize,
                         (int)SMEM_EDGE_BYTES);

    prep_kernel<<<648, 256>>>(nodes, W1a, W2a, W1m, W2m, W1u);

    dim3 gridB(256, 16);
    edge_kernel<<<gridB, 256, SMEM_EDGE_BYTES>>>(edges, mask,
                                                 b1a, b2a, b1m, b2m,
                                                 gamma_e, beta_e, mean_e, var_e,
                                                 edges_out);

    node_kernel<<<512, 256>>>(W1u, b1u, W2u, b2u,
                              gamma_n, beta_n, mean_n, var_n,
                              nodes_out);
}